// round 1
// baseline (speedup 1.0000x reference)
#include <cuda_runtime.h>
#include <cstdint>
#include <cstddef>

#define BDIM 128
#define SLEN 2048
#define NBATCH 32

// 1/sqrt(128)
#define INV_TEMP 0.08838834764831845f

// ---------------------------------------------------------------------------
// Kernel 1: scores = causal_mask(Q @ K^T / sqrt(D)), written into the
// attention region of d_out. Masked entries written as 0.0f.
// Grid: (kt=32, qt=32, b=32), 64x64 tile per CTA, 256 threads.
// ---------------------------------------------------------------------------
__global__ __launch_bounds__(256) void score_kernel(
    const float* __restrict__ Q,
    const float* __restrict__ K,
    float* __restrict__ attn)
{
    const int kt = blockIdx.x;
    const int qt = blockIdx.y;
    const int b  = blockIdx.z;
    const int tid = threadIdx.x;

    float* out = attn + (size_t)b * SLEN * SLEN + (size_t)(qt * 64) * SLEN + kt * 64;

    if (kt > qt) {
        // fully masked tile: write zeros (d_out is poisoned, must be 0)
        const int row = tid >> 2;          // 0..63
        const int c0  = tid & 3;           // 0..3
        float4 z = make_float4(0.f, 0.f, 0.f, 0.f);
        float4* o = reinterpret_cast<float4*>(out + (size_t)row * SLEN);
#pragma unroll
        for (int i = 0; i < 4; i++) o[c0 + 4 * i] = z;
        return;
    }

    __shared__ float As[16][65];   // As[kk][m]  (Q transposed chunk)
    __shared__ float Bs[16][65];   // Bs[kk][n]  (K transposed chunk)

    const int ty = tid >> 4;       // 0..15  (m block)
    const int tx = tid & 15;       // 0..15  (n block)

    float acc[4][4] = {};

    const float* qg = Q + (size_t)b * SLEN * BDIM + (size_t)(qt * 64) * BDIM;
    const float* kg = K + (size_t)b * SLEN * BDIM + (size_t)(kt * 64) * BDIM;

    const int lrow = tid >> 2;         // 0..63
    const int lcol = (tid & 3) * 4;    // 0,4,8,12

    for (int kc = 0; kc < BDIM; kc += 16) {
        float4 aq = *reinterpret_cast<const float4*>(qg + (size_t)lrow * BDIM + kc + lcol);
        float4 ak = *reinterpret_cast<const float4*>(kg + (size_t)lrow * BDIM + kc + lcol);
        __syncthreads();
        As[lcol + 0][lrow] = aq.x; As[lcol + 1][lrow] = aq.y;
        As[lcol + 2][lrow] = aq.z; As[lcol + 3][lrow] = aq.w;
        Bs[lcol + 0][lrow] = ak.x; Bs[lcol + 1][lrow] = ak.y;
        Bs[lcol + 2][lrow] = ak.z; Bs[lcol + 3][lrow] = ak.w;
        __syncthreads();
#pragma unroll
        for (int kk = 0; kk < 16; kk++) {
            float a[4], bb[4];
#pragma unroll
            for (int i = 0; i < 4; i++) a[i] = As[kk][ty * 4 + i];
#pragma unroll
            for (int j = 0; j < 4; j++) bb[j] = Bs[kk][tx * 4 + j];
#pragma unroll
            for (int i = 0; i < 4; i++)
#pragma unroll
                for (int j = 0; j < 4; j++)
                    acc[i][j] = fmaf(a[i], bb[j], acc[i][j]);
        }
    }

    // write with scale + causal mask (only diagonal tiles have masked entries)
#pragma unroll
    for (int i = 0; i < 4; i++) {
        const int gi  = qt * 64 + ty * 4 + i;   // global query index
        const int gj0 = kt * 64 + tx * 4;       // global key index of .x
        float4 r;
        r.x = (gj0 + 0 <= gi) ? acc[i][0] * INV_TEMP : 0.0f;
        r.y = (gj0 + 1 <= gi) ? acc[i][1] * INV_TEMP : 0.0f;
        r.z = (gj0 + 2 <= gi) ? acc[i][2] * INV_TEMP : 0.0f;
        r.w = (gj0 + 3 <= gi) ? acc[i][3] * INV_TEMP : 0.0f;
        *reinterpret_cast<float4*>(out + (size_t)(ty * 4 + i) * SLEN + tx * 4) = r;
    }
}

// ---------------------------------------------------------------------------
// Kernel 2: in-place row softmax over attn[b, i, 0..i]. One CTA (256 thr)
// per query row; the row (<=2048 elems) lives in registers (8/thread).
// ---------------------------------------------------------------------------
__global__ __launch_bounds__(256) void softmax_kernel(float* __restrict__ attn)
{
    const int row = blockIdx.x;           // 0..65535
    const int b = row >> 11;
    const int i = row & 2047;
    float* p = attn + (size_t)b * SLEN * SLEN + (size_t)i * SLEN;
    const int n = i + 1;
    const int tid = threadIdx.x;

    float vals[8];
    float m = -1e30f;
#pragma unroll
    for (int t = 0; t < 8; t++) {
        const int j = tid + t * 256;
        if (j < n) {
            vals[t] = p[j];
            m = fmaxf(m, vals[t]);
        }
    }

    __shared__ float red[256];
    red[tid] = m;
    __syncthreads();
#pragma unroll
    for (int s = 128; s > 0; s >>= 1) {
        if (tid < s) red[tid] = fmaxf(red[tid], red[tid + s]);
        __syncthreads();
    }
    m = red[0];
    __syncthreads();

    float sum = 0.f;
#pragma unroll
    for (int t = 0; t < 8; t++) {
        const int j = tid + t * 256;
        if (j < n) {
            vals[t] = __expf(vals[t] - m);
            sum += vals[t];
        }
    }
    red[tid] = sum;
    __syncthreads();
#pragma unroll
    for (int s = 128; s > 0; s >>= 1) {
        if (tid < s) red[tid] += red[tid + s];
        __syncthreads();
    }
    const float inv = 1.0f / red[0];

#pragma unroll
    for (int t = 0; t < 8; t++) {
        const int j = tid + t * 256;
        if (j < n) p[j] = vals[t] * inv;
    }
}

// ---------------------------------------------------------------------------
// Kernel 3: context = P @ V. Output tile 64 (queries) x 128 (dims) per CTA.
// Accumulates over keys 0 .. (qt*64+63) only (causal skip; masked P entries
// inside the diagonal tile are exactly 0 so it's safe to include them).
// Grid: (qt=32, b=32), 256 threads, each computes 4x8 outputs.
// ---------------------------------------------------------------------------
__global__ __launch_bounds__(256) void pv_kernel(
    const float* __restrict__ attn,
    const float* __restrict__ V,
    float* __restrict__ ctx)
{
    const int qt = blockIdx.x;
    const int b  = blockIdx.y;
    const int tid = threadIdx.x;

    __shared__ float Ps[32][65];    // Ps[kk][m]
    __shared__ float Vs[32][128];   // Vs[kk][n]

    const int ty = tid >> 4;        // 0..15 (m block, x4)
    const int tx = tid & 15;        // 0..15 (n block, x8)

    float acc[4][8] = {};

    const float* pg = attn + (size_t)b * SLEN * SLEN + (size_t)(qt * 64) * SLEN;
    const float* vg = V + (size_t)b * SLEN * BDIM;

    // P tile loaders: 64 rows x 32 cols
    const int plrow = tid >> 2;            // 0..63
    const int plcol = (tid & 3) * 8;       // 0,8,16,24
    // V tile loaders: 32 rows x 128 cols
    const int vlrow = tid >> 3;            // 0..31
    const int vlc   = (tid & 7) * 4;       // float index base, step 32 floats

    const int kend = (qt + 1) * 64;
    for (int k0 = 0; k0 < kend; k0 += 32) {
        float4 p0 = *reinterpret_cast<const float4*>(pg + (size_t)plrow * SLEN + k0 + plcol);
        float4 p1 = *reinterpret_cast<const float4*>(pg + (size_t)plrow * SLEN + k0 + plcol + 4);
        float4 v0 = *reinterpret_cast<const float4*>(vg + (size_t)(k0 + vlrow) * BDIM + vlc);
        float4 v1 = *reinterpret_cast<const float4*>(vg + (size_t)(k0 + vlrow) * BDIM + vlc + 32);
        float4 v2 = *reinterpret_cast<const float4*>(vg + (size_t)(k0 + vlrow) * BDIM + vlc + 64);
        float4 v3 = *reinterpret_cast<const float4*>(vg + (size_t)(k0 + vlrow) * BDIM + vlc + 96);
        __syncthreads();
        Ps[plcol + 0][plrow] = p0.x; Ps[plcol + 1][plrow] = p0.y;
        Ps[plcol + 2][plrow] = p0.z; Ps[plcol + 3][plrow] = p0.w;
        Ps[plcol + 4][plrow] = p1.x; Ps[plcol + 5][plrow] = p1.y;
        Ps[plcol + 6][plrow] = p1.z; Ps[plcol + 7][plrow] = p1.w;
        *reinterpret_cast<float4*>(&Vs[vlrow][vlc])      = v0;
        *reinterpret_cast<float4*>(&Vs[vlrow][vlc + 32]) = v1;
        *reinterpret_cast<float4*>(&Vs[vlrow][vlc + 64]) = v2;
        *reinterpret_cast<float4*>(&Vs[vlrow][vlc + 96]) = v3;
        __syncthreads();
#pragma unroll
        for (int kk = 0; kk < 32; kk++) {
            float a[4];
#pragma unroll
            for (int i = 0; i < 4; i++) a[i] = Ps[kk][ty * 4 + i];
            float4 b0 = *reinterpret_cast<const float4*>(&Vs[kk][tx * 8]);
            float4 b1 = *reinterpret_cast<const float4*>(&Vs[kk][tx * 8 + 4]);
            const float bb[8] = {b0.x, b0.y, b0.z, b0.w, b1.x, b1.y, b1.z, b1.w};
#pragma unroll
            for (int i = 0; i < 4; i++)
#pragma unroll
                for (int j = 0; j < 8; j++)
                    acc[i][j] = fmaf(a[i], bb[j], acc[i][j]);
        }
    }

    float* og = ctx + (size_t)b * SLEN * BDIM + (size_t)(qt * 64) * BDIM;
#pragma unroll
    for (int i = 0; i < 4; i++) {
        float4 r0 = make_float4(acc[i][0], acc[i][1], acc[i][2], acc[i][3]);
        float4 r1 = make_float4(acc[i][4], acc[i][5], acc[i][6], acc[i][7]);
        float* orow = og + (size_t)(ty * 4 + i) * BDIM + tx * 8;
        *reinterpret_cast<float4*>(orow)     = r0;
        *reinterpret_cast<float4*>(orow + 4) = r1;
    }
}

// ---------------------------------------------------------------------------
// Launch
// ---------------------------------------------------------------------------
extern "C" void kernel_launch(void* const* d_in, const int* in_sizes, int n_in,
                              void* d_out, int out_size)
{
    const float* q = (const float*)d_in[0];
    const float* k = (const float*)d_in[1];
    const float* v = (const float*)d_in[2];

    float* ctx  = (float*)d_out;
    float* attn = ctx + (size_t)NBATCH * SLEN * BDIM;  // context first, attention second

    dim3 g1(SLEN / 64, SLEN / 64, NBATCH);   // (kt, qt, b)
    score_kernel<<<g1, 256>>>(q, k, attn);

    softmax_kernel<<<NBATCH * SLEN, 256>>>(attn);

    dim3 g3(SLEN / 64, NBATCH);              // (qt, b)
    pv_kernel<<<g3, 256>>>(attn, v, ctx);
}

// round 2
// speedup vs baseline: 1.3223x; 1.3223x over previous
#include <cuda_runtime.h>
#include <cstdint>
#include <cstddef>

#define BDIM 128
#define SLEN 2048
#define NBATCH 32
#define INV_TEMP 0.08838834764831845f   // 1/sqrt(128)

// ===========================================================================
// Kernel 1: scores = causal_mask(Q @ K^T / sqrt(D)) -> attn region.
// 128x128 tile per CTA, 256 threads, 8x8 register blocking, BK=16,
// vectorized LDS.128, register prefetch double-buffering of global loads.
// Grid: (kt=16, qt=16, b=32).
// ===========================================================================
__global__ __launch_bounds__(256) void score_kernel(
    const float* __restrict__ Q,
    const float* __restrict__ K,
    float* __restrict__ attn)
{
    const int kt = blockIdx.x;
    const int qt = blockIdx.y;
    const int b  = blockIdx.z;
    const int tid = threadIdx.x;

    float* out = attn + (size_t)b * SLEN * SLEN + (size_t)(qt * 128) * SLEN + kt * 128;

    if (kt > qt) {
        // fully masked tile: zero-fill 128x128
        const float4 z = make_float4(0.f, 0.f, 0.f, 0.f);
#pragma unroll
        for (int it = 0; it < 16; it++) {
            const int flat = tid + it * 256;       // 0..4095 float4 slots
            const int r  = flat >> 5;              // 0..127
            const int c4 = flat & 31;              // 0..31
            *reinterpret_cast<float4*>(out + (size_t)r * SLEN + c4 * 4) = z;
        }
        return;
    }

    __shared__ float As[16][132];   // [kk][m], pad keeps rows 16B-aligned
    __shared__ float Bs[16][132];   // [kk][n]

    const float* qg = Q + ((size_t)b * SLEN + qt * 128) * BDIM;
    const float* kg = K + ((size_t)b * SLEN + kt * 128) * BDIM;

    // loaders: 128 rows x 16 cols per tile = 512 float4, 2 per thread
    const int m0 = tid >> 2;        // 0..63
    const int cg = tid & 3;         // col group (x4 floats)

    float4 ra[2], rb[2];
#pragma unroll
    for (int it = 0; it < 2; it++) {
        const int m = m0 + it * 64;
        ra[it] = *reinterpret_cast<const float4*>(qg + (size_t)m * BDIM + cg * 4);
        rb[it] = *reinterpret_cast<const float4*>(kg + (size_t)m * BDIM + cg * 4);
    }

    const int ty = tid >> 4;        // 0..15 (rows, x8)
    const int tx = tid & 15;        // 0..15 (cols, x8)

    float acc[8][8] = {};

    for (int c = 0; c < 8; c++) {
        __syncthreads();
#pragma unroll
        for (int it = 0; it < 2; it++) {
            const int m = m0 + it * 64;
            As[cg * 4 + 0][m] = ra[it].x; As[cg * 4 + 1][m] = ra[it].y;
            As[cg * 4 + 2][m] = ra[it].z; As[cg * 4 + 3][m] = ra[it].w;
            Bs[cg * 4 + 0][m] = rb[it].x; Bs[cg * 4 + 1][m] = rb[it].y;
            Bs[cg * 4 + 2][m] = rb[it].z; Bs[cg * 4 + 3][m] = rb[it].w;
        }
        __syncthreads();
        if (c < 7) {
            const int kc = (c + 1) * 16;
#pragma unroll
            for (int it = 0; it < 2; it++) {
                const int m = m0 + it * 64;
                ra[it] = *reinterpret_cast<const float4*>(qg + (size_t)m * BDIM + kc + cg * 4);
                rb[it] = *reinterpret_cast<const float4*>(kg + (size_t)m * BDIM + kc + cg * 4);
            }
        }
#pragma unroll
        for (int kk = 0; kk < 16; kk++) {
            float4 a0 = *reinterpret_cast<const float4*>(&As[kk][ty * 8]);
            float4 a1 = *reinterpret_cast<const float4*>(&As[kk][ty * 8 + 4]);
            float4 b0 = *reinterpret_cast<const float4*>(&Bs[kk][tx * 8]);
            float4 b1 = *reinterpret_cast<const float4*>(&Bs[kk][tx * 8 + 4]);
            const float av[8] = {a0.x, a0.y, a0.z, a0.w, a1.x, a1.y, a1.z, a1.w};
            const float bv[8] = {b0.x, b0.y, b0.z, b0.w, b1.x, b1.y, b1.z, b1.w};
#pragma unroll
            for (int i = 0; i < 8; i++)
#pragma unroll
                for (int j = 0; j < 8; j++)
                    acc[i][j] = fmaf(av[i], bv[j], acc[i][j]);
        }
    }

    const bool diag = (kt == qt);
#pragma unroll
    for (int i = 0; i < 8; i++) {
        const int ri = ty * 8 + i;                 // row in tile
        float* orow = out + (size_t)ri * SLEN + tx * 8;
        if (!diag) {
            float4 r0 = make_float4(acc[i][0] * INV_TEMP, acc[i][1] * INV_TEMP,
                                    acc[i][2] * INV_TEMP, acc[i][3] * INV_TEMP);
            float4 r1 = make_float4(acc[i][4] * INV_TEMP, acc[i][5] * INV_TEMP,
                                    acc[i][6] * INV_TEMP, acc[i][7] * INV_TEMP);
            *reinterpret_cast<float4*>(orow)     = r0;
            *reinterpret_cast<float4*>(orow + 4) = r1;
        } else {
            const int gi = qt * 128 + ri;
            const int gj0 = kt * 128 + tx * 8;
            float r[8];
#pragma unroll
            for (int j = 0; j < 8; j++)
                r[j] = (gj0 + j <= gi) ? acc[i][j] * INV_TEMP : 0.0f;
            *reinterpret_cast<float4*>(orow)     = make_float4(r[0], r[1], r[2], r[3]);
            *reinterpret_cast<float4*>(orow + 4) = make_float4(r[4], r[5], r[6], r[7]);
        }
    }
}

// ===========================================================================
// Kernel 2: in-place causal row softmax. One WARP per query row, row held in
// registers (16 x float4 per lane), shuffle-only reductions, no barriers.
// Block 256 = 8 rows. Grid = 65536/8.
// ===========================================================================
__global__ __launch_bounds__(256) void softmax_kernel(float* __restrict__ attn)
{
    const int warp = threadIdx.x >> 5;
    const int lane = threadIdx.x & 31;
    const int row  = blockIdx.x * 8 + warp;
    const int b = row >> 11;
    const int i = row & 2047;
    const int n = i + 1;
    float* p = attn + (size_t)b * SLEN * SLEN + (size_t)i * SLEN;

    const float NEG = -3.4e38f;
    float4 vals[16];
    float m = NEG;

#pragma unroll
    for (int w = 0; w < 16; w++) {
        const int base = (w * 32 + lane) * 4;
        if (base < n) {
            float4 v = *reinterpret_cast<const float4*>(p + base);
            if (base + 1 >= n) v.y = NEG;
            if (base + 2 >= n) v.z = NEG;
            if (base + 3 >= n) v.w = NEG;
            vals[w] = v;
            m = fmaxf(m, fmaxf(fmaxf(v.x, v.y), fmaxf(v.z, v.w)));
        } else {
            vals[w] = make_float4(NEG, NEG, NEG, NEG);
        }
    }
#pragma unroll
    for (int s = 16; s > 0; s >>= 1)
        m = fmaxf(m, __shfl_xor_sync(0xffffffffu, m, s));

    float sum = 0.f;
#pragma unroll
    for (int w = 0; w < 16; w++) {
        const int base = (w * 32 + lane) * 4;
        if (base < n) {
            float4 v = vals[w];
            v.x = __expf(v.x - m);   // exp(NEG - m) underflows to 0
            v.y = __expf(v.y - m);
            v.z = __expf(v.z - m);
            v.w = __expf(v.w - m);
            vals[w] = v;
            sum += v.x + v.y + v.z + v.w;
        }
    }
#pragma unroll
    for (int s = 16; s > 0; s >>= 1)
        sum += __shfl_xor_sync(0xffffffffu, sum, s);
    const float inv = 1.0f / sum;

#pragma unroll
    for (int w = 0; w < 16; w++) {
        const int base = (w * 32 + lane) * 4;
        if (base < n) {
            float4 v = vals[w];
            v.x *= inv; v.y *= inv; v.z *= inv; v.w *= inv;
            *reinterpret_cast<float4*>(p + base) = v;   // tail comps write 0 (unchanged)
        }
    }
}

// ===========================================================================
// Kernel 3: context = P @ V. 128x128 output tile per CTA, 256 threads,
// 8x8 blocking, BK=16, causal K-loop skip, reverse-qt scheduling.
// Grid: (qt=16, b=32).
// ===========================================================================
__global__ __launch_bounds__(256) void pv_kernel(
    const float* __restrict__ attn,
    const float* __restrict__ V,
    float* __restrict__ ctx)
{
    const int qt = (int)gridDim.x - 1 - blockIdx.x;   // big tiles first
    const int b  = blockIdx.y;
    const int tid = threadIdx.x;

    __shared__ float Ps[16][132];   // [kk][m] transposed, padded
    __shared__ float Vs[16][128];   // [kk][n] natural

    const float* pg = attn + (size_t)b * SLEN * SLEN + (size_t)(qt * 128) * SLEN;
    const float* vg = V + (size_t)b * SLEN * BDIM;

    // P loaders: 128 rows x 16 cols -> 2 float4/thread
    const int m0 = tid >> 2;
    const int cg = tid & 3;
    // V loaders: 16 rows x 128 cols -> flat float4 index
    const int vrow0 = tid >> 5;          // 0..7 (it adds +8)
    const int vc4   = tid & 31;          // 0..31

    const int nchunks = (qt + 1) * 8;    // keys = (qt+1)*128, BK=16

    float4 rp[2], rv[2];
#pragma unroll
    for (int it = 0; it < 2; it++) {
        rp[it] = *reinterpret_cast<const float4*>(pg + (size_t)(m0 + it * 64) * SLEN + cg * 4);
        rv[it] = *reinterpret_cast<const float4*>(vg + (size_t)(vrow0 + it * 8) * BDIM + vc4 * 4);
    }

    const int ty = tid >> 4;
    const int tx = tid & 15;
    float acc[8][8] = {};

    for (int c = 0; c < nchunks; c++) {
        __syncthreads();
#pragma unroll
        for (int it = 0; it < 2; it++) {
            const int m = m0 + it * 64;
            Ps[cg * 4 + 0][m] = rp[it].x; Ps[cg * 4 + 1][m] = rp[it].y;
            Ps[cg * 4 + 2][m] = rp[it].z; Ps[cg * 4 + 3][m] = rp[it].w;
            *reinterpret_cast<float4*>(&Vs[vrow0 + it * 8][vc4 * 4]) = rv[it];
        }
        __syncthreads();
        if (c + 1 < nchunks) {
            const int k0 = (c + 1) * 16;
#pragma unroll
            for (int it = 0; it < 2; it++) {
                rp[it] = *reinterpret_cast<const float4*>(
                    pg + (size_t)(m0 + it * 64) * SLEN + k0 + cg * 4);
                rv[it] = *reinterpret_cast<const float4*>(
                    vg + (size_t)(k0 + vrow0 + it * 8) * BDIM + vc4 * 4);
            }
        }
#pragma unroll
        for (int kk = 0; kk < 16; kk++) {
            float4 a0 = *reinterpret_cast<const float4*>(&Ps[kk][ty * 8]);
            float4 a1 = *reinterpret_cast<const float4*>(&Ps[kk][ty * 8 + 4]);
            float4 b0 = *reinterpret_cast<const float4*>(&Vs[kk][tx * 8]);
            float4 b1 = *reinterpret_cast<const float4*>(&Vs[kk][tx * 8 + 4]);
            const float av[8] = {a0.x, a0.y, a0.z, a0.w, a1.x, a1.y, a1.z, a1.w};
            const float bv[8] = {b0.x, b0.y, b0.z, b0.w, b1.x, b1.y, b1.z, b1.w};
#pragma unroll
            for (int i = 0; i < 8; i++)
#pragma unroll
                for (int j = 0; j < 8; j++)
                    acc[i][j] = fmaf(av[i], bv[j], acc[i][j]);
        }
    }

    float* og = ctx + ((size_t)b * SLEN + qt * 128) * BDIM;
#pragma unroll
    for (int i = 0; i < 8; i++) {
        float* orow = og + (size_t)(ty * 8 + i) * BDIM + tx * 8;
        *reinterpret_cast<float4*>(orow) =
            make_float4(acc[i][0], acc[i][1], acc[i][2], acc[i][3]);
        *reinterpret_cast<float4*>(orow + 4) =
            make_float4(acc[i][4], acc[i][5], acc[i][6], acc[i][7]);
    }
}

// ===========================================================================
extern "C" void kernel_launch(void* const* d_in, const int* in_sizes, int n_in,
                              void* d_out, int out_size)
{
    const float* q = (const float*)d_in[0];
    const float* k = (const float*)d_in[1];
    const float* v = (const float*)d_in[2];

    float* ctx  = (float*)d_out;
    float* attn = ctx + (size_t)NBATCH * SLEN * BDIM;

    dim3 g1(SLEN / 128, SLEN / 128, NBATCH);   // (kt, qt, b)
    score_kernel<<<g1, 256>>>(q, k, attn);

    softmax_kernel<<<(NBATCH * SLEN) / 8, 256>>>(attn);

    dim3 g3(SLEN / 128, NBATCH);               // (qt, b)
    pv_kernel<<<g3, 256>>>(attn, v, ctx);
}

// round 4
// speedup vs baseline: 2.1447x; 1.6219x over previous
#include <cuda_runtime.h>
#include <cuda_bf16.h>
#include <cstdint>
#include <cstddef>

#define SLEN 2048
#define BDIM 128
#define NBATCH 32
#define INV_TEMP 0.08838834764831845f   // 1/sqrt(128)

// ======================= device scratch (no cudaMalloc) ====================
// V^T split into bf16 hi/lo: layout [b][d][s], s contiguous.
__device__ __nv_bfloat16 g_vt_hi[(size_t)NBATCH * BDIM * SLEN];
__device__ __nv_bfloat16 g_vt_lo[(size_t)NBATCH * BDIM * SLEN];

// =========================== helpers =======================================
__device__ __forceinline__ uint32_t smem_u32(const void* p) {
    uint32_t a;
    asm("{ .reg .u64 t; cvta.to.shared.u64 t, %1; cvt.u32.u64 %0, t; }"
        : "=r"(a) : "l"(p));
    return a;
}

#define LDSM_X4(r0, r1, r2, r3, addr) \
    asm volatile("ldmatrix.sync.aligned.m8n8.x4.shared.b16 {%0,%1,%2,%3}, [%4];" \
        : "=r"(r0), "=r"(r1), "=r"(r2), "=r"(r3) : "r"(addr))

#define MMA_BF16(c, a0, a1, a2, a3, b0, b1) \
    asm volatile("mma.sync.aligned.m16n8k16.row.col.f32.bf16.bf16.f32 " \
        "{%0,%1,%2,%3}, {%4,%5,%6,%7}, {%8,%9}, {%0,%1,%2,%3};" \
        : "+f"((c)[0]), "+f"((c)[1]), "+f"((c)[2]), "+f"((c)[3]) \
        : "r"(a0), "r"(a1), "r"(a2), "r"(a3), "r"(b0), "r"(b1))

#define CP_ASYNC16(dst, src) \
    asm volatile("cp.async.cg.shared.global [%0], [%1], 16;" \
        :: "r"(dst), "l"(src) : "memory")
#define CP_COMMIT  asm volatile("cp.async.commit_group;" ::: "memory")
#define CP_WAIT(n) asm volatile("cp.async.wait_group %0;" :: "n"(n) : "memory")

// A-fragment loader (row-major A, 16x16 bf16 block at (mrow, k0))
template <int STRIDE>
__device__ __forceinline__ void load_a_frag(uint32_t base, int mrow, int k0,
                                            int lane, uint32_t* a) {
    uint32_t off = (uint32_t)((mrow + (lane & 15)) * STRIDE + k0 + ((lane >> 4) << 3));
    LDSM_X4(a[0], a[1], a[2], a[3], base + (off << 1));
}

// B-fragment pair loader: two n8-tiles (16 n rows) x k16 from [N][K] row-major.
// Returns frag(n even)={b[0],b[1]}, frag(n odd)={b[2],b[3]}.
template <int STRIDE>
__device__ __forceinline__ void load_b_pair(uint32_t base, int nrow, int k0,
                                            int lane, uint32_t* b) {
    int g = lane >> 3;
    uint32_t off = (uint32_t)((nrow + ((g & 2) << 2) + (lane & 7)) * STRIDE
                              + k0 + ((g & 1) << 3));
    LDSM_X4(b[0], b[1], b[2], b[3], base + (off << 1));
}

// split 8 fp32 -> bf16 hi/lo packed uint4s
__device__ __forceinline__ void cvt8(const float4& x0, const float4& x1,
                                     uint4& hi, uint4& lo) {
    float v[8] = {x0.x, x0.y, x0.z, x0.w, x1.x, x1.y, x1.z, x1.w};
    uint32_t hb[8], lb[8];
#pragma unroll
    for (int j = 0; j < 8; j++) {
        __nv_bfloat16 h = __float2bfloat16(v[j]);
        float r = v[j] - __bfloat162float(h);
        __nv_bfloat16 l = __float2bfloat16(r);
        hb[j] = (uint32_t)__bfloat16_as_ushort(h);
        lb[j] = (uint32_t)__bfloat16_as_ushort(l);
    }
    hi = make_uint4(hb[0] | (hb[1] << 16), hb[2] | (hb[3] << 16),
                    hb[4] | (hb[5] << 16), hb[6] | (hb[7] << 16));
    lo = make_uint4(lb[0] | (lb[1] << 16), lb[2] | (lb[3] << 16),
                    lb[4] | (lb[5] << 16), lb[6] | (lb[7] << 16));
}

// fast exp on FMA/ALU pipes (no MUFU): 2^f Taylor deg-6, rel err ~1e-7
__device__ __forceinline__ float fast_exp(float x) {
    x = fmaxf(x, -87.0f);
    float y = x * 1.4426950408889634f;
    float t = y + 12582912.0f;                       // round-to-nearest magic
    int   ni = __float_as_int(t) - 0x4B400000;
    float nf = t - 12582912.0f;
    float f = y - nf;                                // f in [-0.5, 0.5]
    float p = 1.5403530e-4f;
    p = fmaf(p, f, 1.3333558e-3f);
    p = fmaf(p, f, 9.6181291e-3f);
    p = fmaf(p, f, 5.5504109e-2f);
    p = fmaf(p, f, 2.4022651e-1f);
    p = fmaf(p, f, 6.9314718e-1f);
    p = fmaf(p, f, 1.0f);
    return p * __int_as_float((ni + 127) << 23);
}

// =============== kernel 0: V -> V^T bf16 hi/lo scratch ======================
#define VT_SMEM (128 * 132 * 4)
__global__ __launch_bounds__(256) void vt_kernel(const float* __restrict__ V) {
    extern __shared__ float ts[];   // [128][132]
    const int st = blockIdx.x, b = blockIdx.y, tid = threadIdx.x;
    const int s0 = st * 128;
    const float* vg = V + ((size_t)b * SLEN + s0) * BDIM;
#pragma unroll
    for (int i = 0; i < 16; i++) {
        int flat = tid + i * 256;
        int row = flat >> 5, c4 = flat & 31;
        float4 x = *reinterpret_cast<const float4*>(vg + (size_t)row * BDIM + c4 * 4);
        *reinterpret_cast<float4*>(ts + row * 132 + c4 * 4) = x;
    }
    __syncthreads();
#pragma unroll
    for (int i = 0; i < 8; i++) {
        int flat = tid + i * 256;
        int d = flat >> 4, sg = (flat & 15) * 8;
        uint32_t hb[8], lb[8];
#pragma unroll
        for (int j = 0; j < 8; j++) {
            float v = ts[(sg + j) * 132 + d];
            __nv_bfloat16 h = __float2bfloat16(v);
            float r = v - __bfloat162float(h);
            __nv_bfloat16 l = __float2bfloat16(r);
            hb[j] = (uint32_t)__bfloat16_as_ushort(h);
            lb[j] = (uint32_t)__bfloat16_as_ushort(l);
        }
        uint4 hi = make_uint4(hb[0] | (hb[1] << 16), hb[2] | (hb[3] << 16),
                              hb[4] | (hb[5] << 16), hb[6] | (hb[7] << 16));
        uint4 lo = make_uint4(lb[0] | (lb[1] << 16), lb[2] | (lb[3] << 16),
                              lb[4] | (lb[5] << 16), lb[6] | (lb[7] << 16));
        size_t idx = ((size_t)b * BDIM + d) * SLEN + s0 + sg;
        *reinterpret_cast<uint4*>(g_vt_hi + idx) = hi;
        *reinterpret_cast<uint4*>(g_vt_lo + idx) = lo;
    }
}

// =============== kernel 1: scores via mma.sync bf16-split ===================
// smem layout (bf16 [128][136] each): A_hi, A_lo, B_hi, B_lo
#define SC_STRIDE 136
#define SC_TILE   (128 * SC_STRIDE * 2)
#define SC_AHI 0
#define SC_ALO (SC_TILE)
#define SC_BHI (2 * SC_TILE)
#define SC_BLO (3 * SC_TILE)
#define SC_SMEM (4 * SC_TILE)

__global__ __launch_bounds__(256) void score_kernel(
    const float* __restrict__ Q,
    const float* __restrict__ K,
    float* __restrict__ attn)
{
    extern __shared__ char sm[];
    const int kt = blockIdx.x, qt = blockIdx.y, b = blockIdx.z;
    const int tid = threadIdx.x, wid = tid >> 5, lane = tid & 31;

    float* out = attn + (size_t)b * SLEN * SLEN + (size_t)(qt * 128) * SLEN + kt * 128;

    if (kt > qt) {   // fully masked tile -> zeros
        const float4 z = make_float4(0.f, 0.f, 0.f, 0.f);
#pragma unroll
        for (int it = 0; it < 16; it++) {
            const int flat = tid + it * 256;
            const int r = flat >> 5, c4 = flat & 31;
            *reinterpret_cast<float4*>(out + (size_t)r * SLEN + c4 * 4) = z;
        }
        return;
    }

    const uint32_t sb = smem_u32(sm);
    const float* qg = Q + ((size_t)b * SLEN + qt * 128) * BDIM;
    const float* kg = K + ((size_t)b * SLEN + kt * 128) * BDIM;

    // fill: convert Q -> A_hi/A_lo, K -> B_hi/B_lo  (row-major, stride 136)
#pragma unroll
    for (int i = 0; i < 8; i++) {
        int flat = tid + i * 256;
        int row = flat >> 4, c8 = (flat & 15) * 8;
        uint32_t dst = (uint32_t)(row * SC_STRIDE + c8) * 2;
        uint4 hi, lo;
        float4 x0 = *reinterpret_cast<const float4*>(qg + (size_t)row * BDIM + c8);
        float4 x1 = *reinterpret_cast<const float4*>(qg + (size_t)row * BDIM + c8 + 4);
        cvt8(x0, x1, hi, lo);
        *reinterpret_cast<uint4*>(sm + SC_AHI + dst) = hi;
        *reinterpret_cast<uint4*>(sm + SC_ALO + dst) = lo;
        x0 = *reinterpret_cast<const float4*>(kg + (size_t)row * BDIM + c8);
        x1 = *reinterpret_cast<const float4*>(kg + (size_t)row * BDIM + c8 + 4);
        cvt8(x0, x1, hi, lo);
        *reinterpret_cast<uint4*>(sm + SC_BHI + dst) = hi;
        *reinterpret_cast<uint4*>(sm + SC_BLO + dst) = lo;
    }
    __syncthreads();

    const int wm = wid & 3;      // 4 warps over M (32 rows each)
    const int wn = wid >> 2;     // 2 warps over N (64 cols each)
    const int mbase = wm * 32;
    const int nbase = wn * 64;

    float acc[2][8][4] = {};

#pragma unroll
    for (int kc = 0; kc < 8; kc++) {
        const int k0 = kc * 16;
        uint32_t bhi[16], blo[16];
#pragma unroll
        for (int jp = 0; jp < 4; jp++) {
            load_b_pair<SC_STRIDE>(sb + SC_BHI, nbase + jp * 16, k0, lane, &bhi[jp * 4]);
            load_b_pair<SC_STRIDE>(sb + SC_BLO, nbase + jp * 16, k0, lane, &blo[jp * 4]);
        }
#pragma unroll
        for (int mt = 0; mt < 2; mt++) {
            uint32_t ahi[4], alo[4];
            load_a_frag<SC_STRIDE>(sb + SC_AHI, mbase + mt * 16, k0, lane, ahi);
            load_a_frag<SC_STRIDE>(sb + SC_ALO, mbase + mt * 16, k0, lane, alo);
#pragma unroll
            for (int nt = 0; nt < 8; nt++) {
                MMA_BF16(acc[mt][nt], ahi[0], ahi[1], ahi[2], ahi[3], bhi[nt * 2], bhi[nt * 2 + 1]);
                MMA_BF16(acc[mt][nt], ahi[0], ahi[1], ahi[2], ahi[3], blo[nt * 2], blo[nt * 2 + 1]);
                MMA_BF16(acc[mt][nt], alo[0], alo[1], alo[2], alo[3], bhi[nt * 2], bhi[nt * 2 + 1]);
            }
        }
    }

    // epilogue: scale + causal mask + store
    const bool diag = (kt == qt);
#pragma unroll
    for (int mt = 0; mt < 2; mt++) {
        const int r0 = mbase + mt * 16 + (lane >> 2);
#pragma unroll
        for (int nt = 0; nt < 8; nt++) {
            const int col = nbase + nt * 8 + (lane & 3) * 2;
#pragma unroll
            for (int h = 0; h < 2; h++) {
                const int r = r0 + h * 8;
                float v0 = acc[mt][nt][h * 2 + 0] * INV_TEMP;
                float v1 = acc[mt][nt][h * 2 + 1] * INV_TEMP;
                if (diag) {
                    if (col + 0 > r) v0 = 0.f;   // same tile => global compare == local
                    if (col + 1 > r) v1 = 0.f;
                }
                *reinterpret_cast<float2*>(out + (size_t)r * SLEN + col) =
                    make_float2(v0, v1);
            }
        }
    }
}

// =============== kernel 2: causal row softmax (poly exp) ====================
__global__ __launch_bounds__(256) void softmax_kernel(float* __restrict__ attn)
{
    const int warp = threadIdx.x >> 5;
    const int lane = threadIdx.x & 31;
    const int row  = blockIdx.x * 8 + warp;
    const int b = row >> 11;
    const int i = row & 2047;
    const int n = i + 1;
    float* p = attn + (size_t)b * SLEN * SLEN + (size_t)i * SLEN;

    const float NEG = -3.4e38f;
    float4 vals[16];
    float m = NEG;
#pragma unroll
    for (int w = 0; w < 16; w++) {
        const int base = (w * 32 + lane) * 4;
        if (base < n) {
            float4 v = *reinterpret_cast<const float4*>(p + base);
            if (base + 1 >= n) v.y = NEG;
            if (base + 2 >= n) v.z = NEG;
            if (base + 3 >= n) v.w = NEG;
            vals[w] = v;
            m = fmaxf(m, fmaxf(fmaxf(v.x, v.y), fmaxf(v.z, v.w)));
        } else {
            vals[w] = make_float4(NEG, NEG, NEG, NEG);
        }
    }
#pragma unroll
    for (int s = 16; s > 0; s >>= 1)
        m = fmaxf(m, __shfl_xor_sync(0xffffffffu, m, s));

    float sum = 0.f;
#pragma unroll
    for (int w = 0; w < 16; w++) {
        const int base = (w * 32 + lane) * 4;
        if (base < n) {
            float4 v = vals[w];
            v.x = fast_exp(v.x - m);
            v.y = (base + 1 < n) ? fast_exp(v.y - m) : 0.f;
            v.z = (base + 2 < n) ? fast_exp(v.z - m) : 0.f;
            v.w = (base + 3 < n) ? fast_exp(v.w - m) : 0.f;
            vals[w] = v;
            sum += v.x + v.y + v.z + v.w;
        }
    }
#pragma unroll
    for (int s = 16; s > 0; s >>= 1)
        sum += __shfl_xor_sync(0xffffffffu, sum, s);
    const float inv = 1.0f / sum;

#pragma unroll
    for (int w = 0; w < 16; w++) {
        const int base = (w * 32 + lane) * 4;
        if (base < n) {
            float4 v = vals[w];
            v.x *= inv; v.y *= inv; v.z *= inv; v.w *= inv;
            *reinterpret_cast<float4*>(p + base) = v;
        }
    }
}

// =============== kernel 3: context = P @ V via mma.sync ====================
// double-buffered k-chunks of 64; per buffer (bf16 [128][72] each):
// P_hi, P_lo, V_hi, V_lo
#define PV_STRIDE 72
#define PV_TILE   (128 * PV_STRIDE * 2)
#define PV_BUF    (4 * PV_TILE)
#define PV_SMEM   (2 * PV_BUF)

__device__ __forceinline__ void pv_fill(char* sm, uint32_t sb, int buf,
                                        const float* pg, int b, int k0, int tid)
{
    char* base = sm + buf * PV_BUF;
    const uint32_t sbase = sb + buf * PV_BUF;
#pragma unroll
    for (int i = 0; i < 4; i++) {
        int flat = tid + i * 256;
        int row = flat >> 3, c8 = (flat & 7) * 8;     // row: 0..127, c8: 0..56
        uint32_t dst = (uint32_t)(row * PV_STRIDE + c8) * 2;
        // V^T hi/lo via cp.async (row = head dim d)
        size_t vidx = ((size_t)b * BDIM + row) * SLEN + k0 + c8;
        CP_ASYNC16(sbase + 2 * PV_TILE + dst, (const char*)(g_vt_hi + vidx));
        CP_ASYNC16(sbase + 3 * PV_TILE + dst, (const char*)(g_vt_lo + vidx));
        // P fp32 -> bf16 split
        float4 x0 = *reinterpret_cast<const float4*>(pg + (size_t)row * SLEN + k0 + c8);
        float4 x1 = *reinterpret_cast<const float4*>(pg + (size_t)row * SLEN + k0 + c8 + 4);
        uint4 hi, lo;
        cvt8(x0, x1, hi, lo);
        *reinterpret_cast<uint4*>(base + dst) = hi;
        *reinterpret_cast<uint4*>(base + PV_TILE + dst) = lo;
    }
}

__global__ __launch_bounds__(256) void pv_kernel(
    const float* __restrict__ attn,
    float* __restrict__ ctx)
{
    extern __shared__ char sm[];
    const int qt = (int)gridDim.x - 1 - blockIdx.x;   // big tiles first
    const int b  = blockIdx.y;
    const int tid = threadIdx.x, wid = tid >> 5, lane = tid & 31;

    const uint32_t sb = smem_u32(sm);
    const float* pg = attn + (size_t)b * SLEN * SLEN + (size_t)(qt * 128) * SLEN;

    const int wm = wid & 3;
    const int wn = wid >> 2;
    const int mbase = wm * 32;
    const int nbase = wn * 64;

    float acc[2][8][4] = {};
    const int nch = (qt + 1) * 2;      // 64-key chunks

    pv_fill(sm, sb, 0, pg, b, 0, tid);
    CP_COMMIT;

    for (int c = 0; c < nch; c++) {
        if (c + 1 < nch) {
            __syncthreads();                      // WAR: prev mma done
            pv_fill(sm, sb, (c + 1) & 1, pg, b, (c + 1) * 64, tid);
            CP_COMMIT;
            CP_WAIT(1);
        } else {
            CP_WAIT(0);
        }
        __syncthreads();

        const uint32_t cb = sb + (c & 1) * PV_BUF;
#pragma unroll
        for (int kc = 0; kc < 4; kc++) {
            const int k0 = kc * 16;
            uint32_t bhi[16], blo[16];
#pragma unroll
            for (int jp = 0; jp < 4; jp++) {
                load_b_pair<PV_STRIDE>(cb + 2 * PV_TILE, nbase + jp * 16, k0, lane, &bhi[jp * 4]);
                load_b_pair<PV_STRIDE>(cb + 3 * PV_TILE, nbase + jp * 16, k0, lane, &blo[jp * 4]);
            }
#pragma unroll
            for (int mt = 0; mt < 2; mt++) {
                uint32_t ahi[4], alo[4];
                load_a_frag<PV_STRIDE>(cb, mbase + mt * 16, k0, lane, ahi);
                load_a_frag<PV_STRIDE>(cb + PV_TILE, mbase + mt * 16, k0, lane, alo);
#pragma unroll
                for (int nt = 0; nt < 8; nt++) {
                    MMA_BF16(acc[mt][nt], ahi[0], ahi[1], ahi[2], ahi[3], bhi[nt * 2], bhi[nt * 2 + 1]);
                    MMA_BF16(acc[mt][nt], ahi[0], ahi[1], ahi[2], ahi[3], blo[nt * 2], blo[nt * 2 + 1]);
                    MMA_BF16(acc[mt][nt], alo[0], alo[1], alo[2], alo[3], bhi[nt * 2], bhi[nt * 2 + 1]);
                }
            }
        }
    }

    float* og = ctx + ((size_t)b * SLEN + qt * 128) * BDIM;
#pragma unroll
    for (int mt = 0; mt < 2; mt++) {
        const int r0 = mbase + mt * 16 + (lane >> 2);
#pragma unroll
        for (int nt = 0; nt < 8; nt++) {
            const int col = nbase + nt * 8 + (lane & 3) * 2;
#pragma unroll
            for (int h = 0; h < 2; h++) {
                const int r = r0 + h * 8;
                *reinterpret_cast<float2*>(og + (size_t)r * BDIM + col) =
                    make_float2(acc[mt][nt][h * 2], acc[mt][nt][h * 2 + 1]);
            }
        }
    }
}

// ============================== launch ======================================
extern "C" void kernel_launch(void* const* d_in, const int* in_sizes, int n_in,
                              void* d_out, int out_size)
{
    const float* q = (const float*)d_in[0];
    const float* k = (const float*)d_in[1];
    const float* v = (const float*)d_in[2];

    float* ctx  = (float*)d_out;
    float* attn = ctx + (size_t)NBATCH * SLEN * BDIM;

    cudaFuncSetAttribute(vt_kernel,    cudaFuncAttributeMaxDynamicSharedMemorySize, VT_SMEM);
    cudaFuncSetAttribute(score_kernel, cudaFuncAttributeMaxDynamicSharedMemorySize, SC_SMEM);
    cudaFuncSetAttribute(pv_kernel,    cudaFuncAttributeMaxDynamicSharedMemorySize, PV_SMEM);

    vt_kernel<<<dim3(SLEN / 128, NBATCH), 256, VT_SMEM>>>(v);
    score_kernel<<<dim3(SLEN / 128, SLEN / 128, NBATCH), 256, SC_SMEM>>>(q, k, attn);
    softmax_kernel<<<(NBATCH * SLEN) / 8, 256>>>(attn);
    pv_kernel<<<dim3(SLEN / 128, NBATCH), 256, PV_SMEM>>>(attn, ctx);
}

// round 5
// speedup vs baseline: 2.2436x; 1.0461x over previous
#include <cuda_runtime.h>
#include <cuda_bf16.h>
#include <cstdint>
#include <cstddef>

#define SLEN 2048
#define BDIM 128
#define NBATCH 32
#define INV_TEMP 0.08838834764831845f   // 1/sqrt(128)

// ======================= device scratch (no cudaMalloc) ====================
__device__ __nv_bfloat16 g_vt_hi[(size_t)NBATCH * BDIM * SLEN];
__device__ __nv_bfloat16 g_vt_lo[(size_t)NBATCH * BDIM * SLEN];
__device__ float g_rowsum[(size_t)NBATCH * SLEN];

// =========================== helpers =======================================
__device__ __forceinline__ uint32_t smem_u32(const void* p) {
    uint32_t a;
    asm("{ .reg .u64 t; cvta.to.shared.u64 t, %1; cvt.u32.u64 %0, t; }"
        : "=r"(a) : "l"(p));
    return a;
}

#define LDSM_X4(r0, r1, r2, r3, addr) \
    asm volatile("ldmatrix.sync.aligned.m8n8.x4.shared.b16 {%0,%1,%2,%3}, [%4];" \
        : "=r"(r0), "=r"(r1), "=r"(r2), "=r"(r3) : "r"(addr))

#define MMA_BF16(c, a0, a1, a2, a3, b0, b1) \
    asm volatile("mma.sync.aligned.m16n8k16.row.col.f32.bf16.bf16.f32 " \
        "{%0,%1,%2,%3}, {%4,%5,%6,%7}, {%8,%9}, {%0,%1,%2,%3};" \
        : "+f"((c)[0]), "+f"((c)[1]), "+f"((c)[2]), "+f"((c)[3]) \
        : "r"(a0), "r"(a1), "r"(a2), "r"(a3), "r"(b0), "r"(b1))

#define CP_ASYNC16(dst, src) \
    asm volatile("cp.async.cg.shared.global [%0], [%1], 16;" \
        :: "r"(dst), "l"(src) : "memory")
#define CP_COMMIT  asm volatile("cp.async.commit_group;" ::: "memory")
#define CP_WAIT(n) asm volatile("cp.async.wait_group %0;" :: "n"(n) : "memory")

template <int STRIDE>
__device__ __forceinline__ void load_a_frag(uint32_t base, int mrow, int k0,
                                            int lane, uint32_t* a) {
    uint32_t off = (uint32_t)((mrow + (lane & 15)) * STRIDE + k0 + ((lane >> 4) << 3));
    LDSM_X4(a[0], a[1], a[2], a[3], base + (off << 1));
}

template <int STRIDE>
__device__ __forceinline__ void load_b_pair(uint32_t base, int nrow, int k0,
                                            int lane, uint32_t* b) {
    int g = lane >> 3;
    uint32_t off = (uint32_t)((nrow + ((g & 2) << 2) + (lane & 7)) * STRIDE
                              + k0 + ((g & 1) << 3));
    LDSM_X4(b[0], b[1], b[2], b[3], base + (off << 1));
}

// split 8 fp32 -> bf16 hi/lo packed uint4s
__device__ __forceinline__ void cvt8(const float4& x0, const float4& x1,
                                     uint4& hi, uint4& lo) {
    float v[8] = {x0.x, x0.y, x0.z, x0.w, x1.x, x1.y, x1.z, x1.w};
    uint32_t hb[8], lb[8];
#pragma unroll
    for (int j = 0; j < 8; j++) {
        __nv_bfloat16 h = __float2bfloat16(v[j]);
        float r = v[j] - __bfloat162float(h);
        __nv_bfloat16 l = __float2bfloat16(r);
        hb[j] = (uint32_t)__bfloat16_as_ushort(h);
        lb[j] = (uint32_t)__bfloat16_as_ushort(l);
    }
    hi = make_uint4(hb[0] | (hb[1] << 16), hb[2] | (hb[3] << 16),
                    hb[4] | (hb[5] << 16), hb[6] | (hb[7] << 16));
    lo = make_uint4(lb[0] | (lb[1] << 16), lb[2] | (lb[3] << 16),
                    lb[4] | (lb[5] << 16), lb[6] | (lb[7] << 16));
}

// fast exp on FMA/ALU pipes (no MUFU): 2^f poly deg-6, rel err ~1e-7
__device__ __forceinline__ float fast_exp(float x) {
    x = fmaxf(x, -87.0f);
    float y = x * 1.4426950408889634f;
    float t = y + 12582912.0f;
    int   ni = __float_as_int(t) - 0x4B400000;
    float nf = t - 12582912.0f;
    float f = y - nf;
    float p = 1.5403530e-4f;
    p = fmaf(p, f, 1.3333558e-3f);
    p = fmaf(p, f, 9.6181291e-3f);
    p = fmaf(p, f, 5.5504109e-2f);
    p = fmaf(p, f, 2.4022651e-1f);
    p = fmaf(p, f, 6.9314718e-1f);
    p = fmaf(p, f, 1.0f);
    return p * __int_as_float((ni + 127) << 23);
}

// =============== kernel 0a: zero row sums ==================================
__global__ __launch_bounds__(256) void zsum_kernel() {
    const int idx = (blockIdx.x * 256 + threadIdx.x) * 4;
    *reinterpret_cast<float4*>(g_rowsum + idx) = make_float4(0.f, 0.f, 0.f, 0.f);
}

// =============== kernel 0b: V -> V^T bf16 hi/lo scratch =====================
#define VT_SMEM (128 * 132 * 4)
__global__ __launch_bounds__(256) void vt_kernel(const float* __restrict__ V) {
    extern __shared__ float ts[];   // [128][132]
    const int st = blockIdx.x, b = blockIdx.y, tid = threadIdx.x;
    const int s0 = st * 128;
    const float* vg = V + ((size_t)b * SLEN + s0) * BDIM;
#pragma unroll
    for (int i = 0; i < 16; i++) {
        int flat = tid + i * 256;
        int row = flat >> 5, c4 = flat & 31;
        float4 x = *reinterpret_cast<const float4*>(vg + (size_t)row * BDIM + c4 * 4);
        *reinterpret_cast<float4*>(ts + row * 132 + c4 * 4) = x;
    }
    __syncthreads();
#pragma unroll
    for (int i = 0; i < 8; i++) {
        int flat = tid + i * 256;
        int d = flat >> 4, sg = (flat & 15) * 8;
        uint32_t hb[8], lb[8];
#pragma unroll
        for (int j = 0; j < 8; j++) {
            float v = ts[(sg + j) * 132 + d];
            __nv_bfloat16 h = __float2bfloat16(v);
            float r = v - __bfloat162float(h);
            __nv_bfloat16 l = __float2bfloat16(r);
            hb[j] = (uint32_t)__bfloat16_as_ushort(h);
            lb[j] = (uint32_t)__bfloat16_as_ushort(l);
        }
        uint4 hi = make_uint4(hb[0] | (hb[1] << 16), hb[2] | (hb[3] << 16),
                              hb[4] | (hb[5] << 16), hb[6] | (hb[7] << 16));
        uint4 lo = make_uint4(lb[0] | (lb[1] << 16), lb[2] | (lb[3] << 16),
                              lb[4] | (lb[5] << 16), lb[6] | (lb[7] << 16));
        size_t idx = ((size_t)b * BDIM + d) * SLEN + s0 + sg;
        *reinterpret_cast<uint4*>(g_vt_hi + idx) = hi;
        *reinterpret_cast<uint4*>(g_vt_lo + idx) = lo;
    }
}

// ====== kernel 1: E = exp(causal(QK^T/sqrt(D))) + per-row sum atomics =======
#define SC_STRIDE 136
#define SC_TILE   (128 * SC_STRIDE * 2)
#define SC_AHI 0
#define SC_ALO (SC_TILE)
#define SC_BHI (2 * SC_TILE)
#define SC_BLO (3 * SC_TILE)
#define SC_SMEM (4 * SC_TILE)

__global__ __launch_bounds__(256) void score_kernel(
    const float* __restrict__ Q,
    const float* __restrict__ K,
    float* __restrict__ attn)
{
    extern __shared__ char sm[];
    const int kt = blockIdx.x, qt = blockIdx.y, b = blockIdx.z;
    const int tid = threadIdx.x, wid = tid >> 5, lane = tid & 31;

    float* out = attn + (size_t)b * SLEN * SLEN + (size_t)(qt * 128) * SLEN + kt * 128;

    if (kt > qt) {   // fully masked tile -> zeros
        const float4 z = make_float4(0.f, 0.f, 0.f, 0.f);
#pragma unroll
        for (int it = 0; it < 16; it++) {
            const int flat = tid + it * 256;
            const int r = flat >> 5, c4 = flat & 31;
            *reinterpret_cast<float4*>(out + (size_t)r * SLEN + c4 * 4) = z;
        }
        return;
    }

    const uint32_t sb = smem_u32(sm);
    const float* qg = Q + ((size_t)b * SLEN + qt * 128) * BDIM;
    const float* kg = K + ((size_t)b * SLEN + kt * 128) * BDIM;

#pragma unroll
    for (int i = 0; i < 8; i++) {
        int flat = tid + i * 256;
        int row = flat >> 4, c8 = (flat & 15) * 8;
        uint32_t dst = (uint32_t)(row * SC_STRIDE + c8) * 2;
        uint4 hi, lo;
        float4 x0 = *reinterpret_cast<const float4*>(qg + (size_t)row * BDIM + c8);
        float4 x1 = *reinterpret_cast<const float4*>(qg + (size_t)row * BDIM + c8 + 4);
        cvt8(x0, x1, hi, lo);
        *reinterpret_cast<uint4*>(sm + SC_AHI + dst) = hi;
        *reinterpret_cast<uint4*>(sm + SC_ALO + dst) = lo;
        x0 = *reinterpret_cast<const float4*>(kg + (size_t)row * BDIM + c8);
        x1 = *reinterpret_cast<const float4*>(kg + (size_t)row * BDIM + c8 + 4);
        cvt8(x0, x1, hi, lo);
        *reinterpret_cast<uint4*>(sm + SC_BHI + dst) = hi;
        *reinterpret_cast<uint4*>(sm + SC_BLO + dst) = lo;
    }
    __syncthreads();

    const int wm = wid & 3;
    const int wn = wid >> 2;
    const int mbase = wm * 32;
    const int nbase = wn * 64;

    float acc[2][8][4] = {};

#pragma unroll
    for (int kc = 0; kc < 8; kc++) {
        const int k0 = kc * 16;
        uint32_t bhi[16], blo[16];
#pragma unroll
        for (int jp = 0; jp < 4; jp++) {
            load_b_pair<SC_STRIDE>(sb + SC_BHI, nbase + jp * 16, k0, lane, &bhi[jp * 4]);
            load_b_pair<SC_STRIDE>(sb + SC_BLO, nbase + jp * 16, k0, lane, &blo[jp * 4]);
        }
#pragma unroll
        for (int mt = 0; mt < 2; mt++) {
            uint32_t ahi[4], alo[4];
            load_a_frag<SC_STRIDE>(sb + SC_AHI, mbase + mt * 16, k0, lane, ahi);
            load_a_frag<SC_STRIDE>(sb + SC_ALO, mbase + mt * 16, k0, lane, alo);
#pragma unroll
            for (int nt = 0; nt < 8; nt++) {
                MMA_BF16(acc[mt][nt], ahi[0], ahi[1], ahi[2], ahi[3], bhi[nt * 2], bhi[nt * 2 + 1]);
                MMA_BF16(acc[mt][nt], ahi[0], ahi[1], ahi[2], ahi[3], blo[nt * 2], blo[nt * 2 + 1]);
                MMA_BF16(acc[mt][nt], alo[0], alo[1], alo[2], alo[3], bhi[nt * 2], bhi[nt * 2 + 1]);
            }
        }
    }

    // epilogue: exp(scale*acc) + causal mask + store + row-sum atomics
    const bool diag = (kt == qt);
    float rsum[2][2] = {};   // [mt][h]
#pragma unroll
    for (int mt = 0; mt < 2; mt++) {
        const int r0 = mbase + mt * 16 + (lane >> 2);
#pragma unroll
        for (int nt = 0; nt < 8; nt++) {
            const int col = nbase + nt * 8 + (lane & 3) * 2;
#pragma unroll
            for (int h = 0; h < 2; h++) {
                const int r = r0 + h * 8;
                float v0 = fast_exp(acc[mt][nt][h * 2 + 0] * INV_TEMP);
                float v1 = fast_exp(acc[mt][nt][h * 2 + 1] * INV_TEMP);
                if (diag) {
                    if (col + 0 > r) v0 = 0.f;
                    if (col + 1 > r) v1 = 0.f;
                }
                rsum[mt][h] += v0 + v1;
                *reinterpret_cast<float2*>(out + (size_t)r * SLEN + col) =
                    make_float2(v0, v1);
            }
        }
    }
    // reduce cols across the 4 lanes of each quad, then one atomic per row
#pragma unroll
    for (int mt = 0; mt < 2; mt++)
#pragma unroll
        for (int h = 0; h < 2; h++) {
            rsum[mt][h] += __shfl_xor_sync(0xffffffffu, rsum[mt][h], 1);
            rsum[mt][h] += __shfl_xor_sync(0xffffffffu, rsum[mt][h], 2);
        }
    if ((lane & 3) == 0) {
        float* rs = g_rowsum + (size_t)b * SLEN + qt * 128;
#pragma unroll
        for (int mt = 0; mt < 2; mt++)
#pragma unroll
            for (int h = 0; h < 2; h++)
                atomicAdd(rs + mbase + mt * 16 + (lane >> 2) + h * 8, rsum[mt][h]);
    }
}

// ====== kernel 2: ctx = (E/rowsum) @ V; also writes normalized attn ========
#define PV_STRIDE 72
#define PV_TILE   (128 * PV_STRIDE * 2)
#define PV_BUF    (4 * PV_TILE)
#define PV_SMEM   (2 * PV_BUF)

__device__ __forceinline__ void pv_fill(char* sm, uint32_t sb, int buf,
                                        float* pg, const float* sinv,
                                        int b, int k0, int tid)
{
    char* base = sm + buf * PV_BUF;
    const uint32_t sbase = sb + buf * PV_BUF;
#pragma unroll
    for (int i = 0; i < 4; i++) {
        int flat = tid + i * 256;
        int row = flat >> 3, c8 = (flat & 7) * 8;
        uint32_t dst = (uint32_t)(row * PV_STRIDE + c8) * 2;
        size_t vidx = ((size_t)b * BDIM + row) * SLEN + k0 + c8;
        CP_ASYNC16(sbase + 2 * PV_TILE + dst, (const char*)(g_vt_hi + vidx));
        CP_ASYNC16(sbase + 3 * PV_TILE + dst, (const char*)(g_vt_lo + vidx));
        // P exp tile: normalize, write back, split to bf16
        float* prow = pg + (size_t)row * SLEN + k0 + c8;
        float4 x0 = *reinterpret_cast<const float4*>(prow);
        float4 x1 = *reinterpret_cast<const float4*>(prow + 4);
        const float inv = sinv[row];
        x0.x *= inv; x0.y *= inv; x0.z *= inv; x0.w *= inv;
        x1.x *= inv; x1.y *= inv; x1.z *= inv; x1.w *= inv;
        *reinterpret_cast<float4*>(prow)     = x0;
        *reinterpret_cast<float4*>(prow + 4) = x1;
        uint4 hi, lo;
        cvt8(x0, x1, hi, lo);
        *reinterpret_cast<uint4*>(base + dst) = hi;
        *reinterpret_cast<uint4*>(base + PV_TILE + dst) = lo;
    }
}

__global__ __launch_bounds__(256) void pv_kernel(
    float* __restrict__ attn,
    float* __restrict__ ctx)
{
    extern __shared__ char sm[];
    __shared__ float sinv[128];
    const int qt = (int)gridDim.x - 1 - blockIdx.x;
    const int b  = blockIdx.y;
    const int tid = threadIdx.x, wid = tid >> 5, lane = tid & 31;

    const uint32_t sb = smem_u32(sm);
    float* pg = attn + (size_t)b * SLEN * SLEN + (size_t)(qt * 128) * SLEN;

    if (tid < 128)
        sinv[tid] = 1.0f / g_rowsum[(size_t)b * SLEN + qt * 128 + tid];
    __syncthreads();

    const int wm = wid & 3;
    const int wn = wid >> 2;
    const int mbase = wm * 32;
    const int nbase = wn * 64;

    float acc[2][8][4] = {};
    const int nch = (qt + 1) * 2;

    pv_fill(sm, sb, 0, pg, sinv, b, 0, tid);
    CP_COMMIT;

    for (int c = 0; c < nch; c++) {
        if (c + 1 < nch) {
            __syncthreads();
            pv_fill(sm, sb, (c + 1) & 1, pg, sinv, b, (c + 1) * 64, tid);
            CP_COMMIT;
            CP_WAIT(1);
        } else {
            CP_WAIT(0);
        }
        __syncthreads();

        const uint32_t cb = sb + (c & 1) * PV_BUF;
#pragma unroll
        for (int kc = 0; kc < 4; kc++) {
            const int k0 = kc * 16;
            uint32_t bhi[16], blo[16];
#pragma unroll
            for (int jp = 0; jp < 4; jp++) {
                load_b_pair<PV_STRIDE>(cb + 2 * PV_TILE, nbase + jp * 16, k0, lane, &bhi[jp * 4]);
                load_b_pair<PV_STRIDE>(cb + 3 * PV_TILE, nbase + jp * 16, k0, lane, &blo[jp * 4]);
            }
#pragma unroll
            for (int mt = 0; mt < 2; mt++) {
                uint32_t ahi[4], alo[4];
                load_a_frag<PV_STRIDE>(cb, mbase + mt * 16, k0, lane, ahi);
                load_a_frag<PV_STRIDE>(cb + PV_TILE, mbase + mt * 16, k0, lane, alo);
#pragma unroll
                for (int nt = 0; nt < 8; nt++) {
                    MMA_BF16(acc[mt][nt], ahi[0], ahi[1], ahi[2], ahi[3], bhi[nt * 2], bhi[nt * 2 + 1]);
                    MMA_BF16(acc[mt][nt], ahi[0], ahi[1], ahi[2], ahi[3], blo[nt * 2], blo[nt * 2 + 1]);
                    MMA_BF16(acc[mt][nt], alo[0], alo[1], alo[2], alo[3], bhi[nt * 2], bhi[nt * 2 + 1]);
                }
            }
        }
    }

    float* og = ctx + ((size_t)b * SLEN + qt * 128) * BDIM;
#pragma unroll
    for (int mt = 0; mt < 2; mt++) {
        const int r0 = mbase + mt * 16 + (lane >> 2);
#pragma unroll
        for (int nt = 0; nt < 8; nt++) {
            const int col = nbase + nt * 8 + (lane & 3) * 2;
#pragma unroll
            for (int h = 0; h < 2; h++) {
                const int r = r0 + h * 8;
                *reinterpret_cast<float2*>(og + (size_t)r * BDIM + col) =
                    make_float2(acc[mt][nt][h * 2], acc[mt][nt][h * 2 + 1]);
            }
        }
    }
}

// ============================== launch ======================================
extern "C" void kernel_launch(void* const* d_in, const int* in_sizes, int n_in,
                              void* d_out, int out_size)
{
    const float* q = (const float*)d_in[0];
    const float* k = (const float*)d_in[1];
    const float* v = (const float*)d_in[2];

    float* ctx  = (float*)d_out;
    float* attn = ctx + (size_t)NBATCH * SLEN * BDIM;

    cudaFuncSetAttribute(vt_kernel,    cudaFuncAttributeMaxDynamicSharedMemorySize, VT_SMEM);
    cudaFuncSetAttribute(score_kernel, cudaFuncAttributeMaxDynamicSharedMemorySize, SC_SMEM);
    cudaFuncSetAttribute(pv_kernel,    cudaFuncAttributeMaxDynamicSharedMemorySize, PV_SMEM);

    zsum_kernel<<<(NBATCH * SLEN) / 1024, 256>>>();
    vt_kernel<<<dim3(SLEN / 128, NBATCH), 256, VT_SMEM>>>(v);
    score_kernel<<<dim3(SLEN / 128, SLEN / 128, NBATCH), 256, SC_SMEM>>>(q, k, attn);
    pv_kernel<<<dim3(SLEN / 128, NBATCH), 256, PV_SMEM>>>(attn, ctx);
}

// round 6
// speedup vs baseline: 2.6868x; 1.1975x over previous
#include <cuda_runtime.h>
#include <cuda_bf16.h>
#include <cstdint>
#include <cstddef>

#define SLEN 2048
#define BDIM 128
#define NBATCH 32
#define INV_TEMP 0.08838834764831845f   // 1/sqrt(128)

// ======================= device scratch (no cudaMalloc) ====================
__device__ __nv_bfloat16 g_q_hi[(size_t)NBATCH * SLEN * BDIM];
__device__ __nv_bfloat16 g_q_lo[(size_t)NBATCH * SLEN * BDIM];
__device__ __nv_bfloat16 g_k_hi[(size_t)NBATCH * SLEN * BDIM];
__device__ __nv_bfloat16 g_k_lo[(size_t)NBATCH * SLEN * BDIM];
__device__ __nv_bfloat16 g_vt_hi[(size_t)NBATCH * BDIM * SLEN];
__device__ __nv_bfloat16 g_vt_lo[(size_t)NBATCH * BDIM * SLEN];
__device__ float g_rowsum[(size_t)NBATCH * SLEN];

// =========================== helpers =======================================
__device__ __forceinline__ uint32_t smem_u32(const void* p) {
    uint32_t a;
    asm("{ .reg .u64 t; cvta.to.shared.u64 t, %1; cvt.u32.u64 %0, t; }"
        : "=r"(a) : "l"(p));
    return a;
}

#define LDSM_X4(r0, r1, r2, r3, addr) \
    asm volatile("ldmatrix.sync.aligned.m8n8.x4.shared.b16 {%0,%1,%2,%3}, [%4];" \
        : "=r"(r0), "=r"(r1), "=r"(r2), "=r"(r3) : "r"(addr))

#define MMA_BF16(c, a0, a1, a2, a3, b0, b1) \
    asm volatile("mma.sync.aligned.m16n8k16.row.col.f32.bf16.bf16.f32 " \
        "{%0,%1,%2,%3}, {%4,%5,%6,%7}, {%8,%9}, {%0,%1,%2,%3};" \
        : "+f"((c)[0]), "+f"((c)[1]), "+f"((c)[2]), "+f"((c)[3]) \
        : "r"(a0), "r"(a1), "r"(a2), "r"(a3), "r"(b0), "r"(b1))

#define CP_ASYNC16(dst, src) \
    asm volatile("cp.async.cg.shared.global [%0], [%1], 16;" \
        :: "r"(dst), "l"(src) : "memory")
#define CP_COMMIT  asm volatile("cp.async.commit_group;" ::: "memory")
#define CP_WAIT(n) asm volatile("cp.async.wait_group %0;" :: "n"(n) : "memory")

template <int STRIDE>
__device__ __forceinline__ void load_a_frag(uint32_t base, int mrow, int k0,
                                            int lane, uint32_t* a) {
    uint32_t off = (uint32_t)((mrow + (lane & 15)) * STRIDE + k0 + ((lane >> 4) << 3));
    LDSM_X4(a[0], a[1], a[2], a[3], base + (off << 1));
}

template <int STRIDE>
__device__ __forceinline__ void load_b_pair(uint32_t base, int nrow, int k0,
                                            int lane, uint32_t* b) {
    int g = lane >> 3;
    uint32_t off = (uint32_t)((nrow + ((g & 2) << 2) + (lane & 7)) * STRIDE
                              + k0 + ((g & 1) << 3));
    LDSM_X4(b[0], b[1], b[2], b[3], base + (off << 1));
}

// split 8 fp32 -> bf16 hi/lo packed uint4s
__device__ __forceinline__ void cvt8(const float4& x0, const float4& x1,
                                     uint4& hi, uint4& lo) {
    float v[8] = {x0.x, x0.y, x0.z, x0.w, x1.x, x1.y, x1.z, x1.w};
    uint32_t hb[8], lb[8];
#pragma unroll
    for (int j = 0; j < 8; j++) {
        __nv_bfloat16 h = __float2bfloat16(v[j]);
        float r = v[j] - __bfloat162float(h);
        __nv_bfloat16 l = __float2bfloat16(r);
        hb[j] = (uint32_t)__bfloat16_as_ushort(h);
        lb[j] = (uint32_t)__bfloat16_as_ushort(l);
    }
    hi = make_uint4(hb[0] | (hb[1] << 16), hb[2] | (hb[3] << 16),
                    hb[4] | (hb[5] << 16), hb[6] | (hb[7] << 16));
    lo = make_uint4(lb[0] | (lb[1] << 16), lb[2] | (lb[3] << 16),
                    lb[4] | (lb[5] << 16), lb[6] | (lb[7] << 16));
}

// fast exp on FMA/ALU pipes (no MUFU): 2^f poly deg-6, rel err ~1e-7
__device__ __forceinline__ float fast_exp(float x) {
    x = fmaxf(x, -87.0f);
    float y = x * 1.4426950408889634f;
    float t = y + 12582912.0f;
    int   ni = __float_as_int(t) - 0x4B400000;
    float nf = t - 12582912.0f;
    float f = y - nf;
    float p = 1.5403530e-4f;
    p = fmaf(p, f, 1.3333558e-3f);
    p = fmaf(p, f, 9.6181291e-3f);
    p = fmaf(p, f, 5.5504109e-2f);
    p = fmaf(p, f, 2.4022651e-1f);
    p = fmaf(p, f, 6.9314718e-1f);
    p = fmaf(p, f, 1.0f);
    return p * __int_as_float((ni + 127) << 23);
}

// =============== prep 0: zero row sums ======================================
__global__ __launch_bounds__(256) void zsum_kernel() {
    const int idx = (blockIdx.x * 256 + threadIdx.x) * 4;
    *reinterpret_cast<float4*>(g_rowsum + idx) = make_float4(0.f, 0.f, 0.f, 0.f);
}

// =============== prep 1: split Q,K into bf16 hi/lo scratch ==================
__global__ __launch_bounds__(256) void split_qk_kernel(
    const float* __restrict__ Q, const float* __restrict__ K)
{
    const size_t base = ((size_t)blockIdx.x * 256 + threadIdx.x) * 8;
    uint4 hi, lo;
    float4 x0 = *reinterpret_cast<const float4*>(Q + base);
    float4 x1 = *reinterpret_cast<const float4*>(Q + base + 4);
    cvt8(x0, x1, hi, lo);
    *reinterpret_cast<uint4*>(g_q_hi + base) = hi;
    *reinterpret_cast<uint4*>(g_q_lo + base) = lo;
    x0 = *reinterpret_cast<const float4*>(K + base);
    x1 = *reinterpret_cast<const float4*>(K + base + 4);
    cvt8(x0, x1, hi, lo);
    *reinterpret_cast<uint4*>(g_k_hi + base) = hi;
    *reinterpret_cast<uint4*>(g_k_lo + base) = lo;
}

// =============== prep 2: V -> V^T bf16 hi/lo scratch ========================
#define VT_SMEM (128 * 132 * 4)
__global__ __launch_bounds__(256) void vt_kernel(const float* __restrict__ V) {
    extern __shared__ float ts[];   // [128][132]
    const int st = blockIdx.x, b = blockIdx.y, tid = threadIdx.x;
    const int s0 = st * 128;
    const float* vg = V + ((size_t)b * SLEN + s0) * BDIM;
#pragma unroll
    for (int i = 0; i < 16; i++) {
        int flat = tid + i * 256;
        int row = flat >> 5, c4 = flat & 31;
        float4 x = *reinterpret_cast<const float4*>(vg + (size_t)row * BDIM + c4 * 4);
        *reinterpret_cast<float4*>(ts + row * 132 + c4 * 4) = x;
    }
    __syncthreads();
#pragma unroll
    for (int i = 0; i < 8; i++) {
        int flat = tid + i * 256;
        int d = flat >> 4, sg = (flat & 15) * 8;
        uint32_t hb[8], lb[8];
#pragma unroll
        for (int j = 0; j < 8; j++) {
            float v = ts[(sg + j) * 132 + d];
            __nv_bfloat16 h = __float2bfloat16(v);
            float r = v - __bfloat162float(h);
            __nv_bfloat16 l = __float2bfloat16(r);
            hb[j] = (uint32_t)__bfloat16_as_ushort(h);
            lb[j] = (uint32_t)__bfloat16_as_ushort(l);
        }
        uint4 hi = make_uint4(hb[0] | (hb[1] << 16), hb[2] | (hb[3] << 16),
                              hb[4] | (hb[5] << 16), hb[6] | (hb[7] << 16));
        uint4 lo = make_uint4(lb[0] | (lb[1] << 16), lb[2] | (lb[3] << 16),
                              lb[4] | (lb[5] << 16), lb[6] | (lb[7] << 16));
        size_t idx = ((size_t)b * BDIM + d) * SLEN + s0 + sg;
        *reinterpret_cast<uint4*>(g_vt_hi + idx) = hi;
        *reinterpret_cast<uint4*>(g_vt_lo + idx) = lo;
    }
}

// ====== kernel 1: E = exp(causal(QK^T/sqrt(D))) + per-row sum atomics =======
// 512 threads, 16 warps; warp tile 32(M)x32(N); tiles via cp.async from scratch
#define SC_STRIDE 136
#define SC_TILE   (128 * SC_STRIDE * 2)     // 34816 bytes
#define SC_SMEM   (4 * SC_TILE)             // Qhi, Qlo, Khi, Klo

__global__ __launch_bounds__(512) void score_kernel(float* __restrict__ attn)
{
    extern __shared__ char sm[];
    const int kt = blockIdx.x, qt = blockIdx.y, b = blockIdx.z;
    const int tid = threadIdx.x, wid = tid >> 5, lane = tid & 31;

    float* out = attn + (size_t)b * SLEN * SLEN + (size_t)(qt * 128) * SLEN + kt * 128;

    if (kt > qt) {   // fully masked tile -> zeros
        const float4 z = make_float4(0.f, 0.f, 0.f, 0.f);
#pragma unroll
        for (int it = 0; it < 8; it++) {
            const int flat = tid + it * 512;
            const int r = flat >> 5, c4 = flat & 31;
            *reinterpret_cast<float4*>(out + (size_t)r * SLEN + c4 * 4) = z;
        }
        return;
    }

    const uint32_t sb = smem_u32(sm);
    const size_t qoff = ((size_t)b * SLEN + qt * 128) * BDIM;
    const size_t koff = ((size_t)b * SLEN + kt * 128) * BDIM;
    const __nv_bfloat16* srcs[4] = {g_q_hi + qoff, g_q_lo + qoff,
                                    g_k_hi + koff, g_k_lo + koff};
    // 4 tiles x 128 rows x 16 x 16B; tile index = i>>2 (compile-time per i)
#pragma unroll
    for (int i = 0; i < 16; i++) {
        const int tile = i >> 2;
        const int flat = tid + i * 512;
        const int r = (flat >> 4) & 127, c = flat & 15;
        uint32_t dst = sb + tile * SC_TILE + (uint32_t)(r * SC_STRIDE + c * 8) * 2;
        CP_ASYNC16(dst, srcs[tile] + (size_t)r * BDIM + c * 8);
    }
    CP_COMMIT;
    CP_WAIT(0);
    __syncthreads();

    const int wm = wid & 3;        // 4 m-slices of 32 rows
    const int wn = wid >> 2;       // 4 n-slices of 32 cols
    const int mbase = wm * 32;
    const int nbase = wn * 32;

    float acc[2][4][4] = {};

#pragma unroll
    for (int kc = 0; kc < 8; kc++) {
        const int k0 = kc * 16;
        uint32_t bhi[8], blo[8];
#pragma unroll
        for (int jp = 0; jp < 2; jp++) {
            load_b_pair<SC_STRIDE>(sb + 2 * SC_TILE, nbase + jp * 16, k0, lane, &bhi[jp * 4]);
            load_b_pair<SC_STRIDE>(sb + 3 * SC_TILE, nbase + jp * 16, k0, lane, &blo[jp * 4]);
        }
#pragma unroll
        for (int mt = 0; mt < 2; mt++) {
            uint32_t ahi[4], alo[4];
            load_a_frag<SC_STRIDE>(sb, mbase + mt * 16, k0, lane, ahi);
            load_a_frag<SC_STRIDE>(sb + SC_TILE, mbase + mt * 16, k0, lane, alo);
#pragma unroll
            for (int nt = 0; nt < 4; nt++) {
                MMA_BF16(acc[mt][nt], ahi[0], ahi[1], ahi[2], ahi[3], bhi[nt * 2], bhi[nt * 2 + 1]);
                MMA_BF16(acc[mt][nt], ahi[0], ahi[1], ahi[2], ahi[3], blo[nt * 2], blo[nt * 2 + 1]);
                MMA_BF16(acc[mt][nt], alo[0], alo[1], alo[2], alo[3], bhi[nt * 2], bhi[nt * 2 + 1]);
            }
        }
    }

    // epilogue: exp(scale*acc) + causal mask + store + row-sum atomics
    const bool diag = (kt == qt);
    float rsum[2][2] = {};
#pragma unroll
    for (int mt = 0; mt < 2; mt++) {
        const int r0 = mbase + mt * 16 + (lane >> 2);
#pragma unroll
        for (int nt = 0; nt < 4; nt++) {
            const int col = nbase + nt * 8 + (lane & 3) * 2;
#pragma unroll
            for (int h = 0; h < 2; h++) {
                const int r = r0 + h * 8;
                float v0 = fast_exp(acc[mt][nt][h * 2 + 0] * INV_TEMP);
                float v1 = fast_exp(acc[mt][nt][h * 2 + 1] * INV_TEMP);
                if (diag) {
                    if (col + 0 > r) v0 = 0.f;
                    if (col + 1 > r) v1 = 0.f;
                }
                rsum[mt][h] += v0 + v1;
                *reinterpret_cast<float2*>(out + (size_t)r * SLEN + col) =
                    make_float2(v0, v1);
            }
        }
    }
#pragma unroll
    for (int mt = 0; mt < 2; mt++)
#pragma unroll
        for (int h = 0; h < 2; h++) {
            rsum[mt][h] += __shfl_xor_sync(0xffffffffu, rsum[mt][h], 1);
            rsum[mt][h] += __shfl_xor_sync(0xffffffffu, rsum[mt][h], 2);
        }
    if ((lane & 3) == 0) {
        float* rs = g_rowsum + (size_t)b * SLEN + qt * 128;
#pragma unroll
        for (int mt = 0; mt < 2; mt++)
#pragma unroll
            for (int h = 0; h < 2; h++)
                atomicAdd(rs + mbase + mt * 16 + (lane >> 2) + h * 8, rsum[mt][h]);
    }
}

// ====== kernel 2: ctx = (E/rowsum) @ V; also writes normalized attn ========
// 512 threads, warp tile 32x32, double-buffered 64-key chunks
#define PV_STRIDE 72
#define PV_TILE   (128 * PV_STRIDE * 2)     // 18432 bytes
#define PV_BUF    (4 * PV_TILE)             // Phi, Plo, Vhi, Vlo
#define PV_SMEM   (2 * PV_BUF)              // 147456

__device__ __forceinline__ void pv_fill(char* sm, uint32_t sb, int buf,
                                        float* pg, const float* sinv,
                                        int b, int k0, int tid)
{
    char* base = sm + buf * PV_BUF;
    const uint32_t sbase = sb + buf * PV_BUF;
#pragma unroll
    for (int i = 0; i < 2; i++) {
        int flat = tid + i * 512;
        int row = flat >> 3, c8 = (flat & 7) * 8;
        uint32_t dst = (uint32_t)(row * PV_STRIDE + c8) * 2;
        size_t vidx = ((size_t)b * BDIM + row) * SLEN + k0 + c8;
        CP_ASYNC16(sbase + 2 * PV_TILE + dst, (const char*)(g_vt_hi + vidx));
        CP_ASYNC16(sbase + 3 * PV_TILE + dst, (const char*)(g_vt_lo + vidx));
        // P exp tile: normalize, write back, split to bf16
        float* prow = pg + (size_t)row * SLEN + k0 + c8;
        float4 x0 = *reinterpret_cast<const float4*>(prow);
        float4 x1 = *reinterpret_cast<const float4*>(prow + 4);
        const float inv = sinv[row];
        x0.x *= inv; x0.y *= inv; x0.z *= inv; x0.w *= inv;
        x1.x *= inv; x1.y *= inv; x1.z *= inv; x1.w *= inv;
        *reinterpret_cast<float4*>(prow)     = x0;
        *reinterpret_cast<float4*>(prow + 4) = x1;
        uint4 hi, lo;
        cvt8(x0, x1, hi, lo);
        *reinterpret_cast<uint4*>(base + dst) = hi;
        *reinterpret_cast<uint4*>(base + PV_TILE + dst) = lo;
    }
}

__global__ __launch_bounds__(512) void pv_kernel(
    float* __restrict__ attn,
    float* __restrict__ ctx)
{
    extern __shared__ char sm[];
    __shared__ float sinv[128];
    const int qt = (int)gridDim.x - 1 - blockIdx.x;
    const int b  = blockIdx.y;
    const int tid = threadIdx.x, wid = tid >> 5, lane = tid & 31;

    const uint32_t sb = smem_u32(sm);
    float* pg = attn + (size_t)b * SLEN * SLEN + (size_t)(qt * 128) * SLEN;

    if (tid < 128)
        sinv[tid] = 1.0f / g_rowsum[(size_t)b * SLEN + qt * 128 + tid];
    __syncthreads();

    const int wm = wid & 3;
    const int wn = wid >> 2;
    const int mbase = wm * 32;
    const int nbase = wn * 32;

    float acc[2][4][4] = {};
    const int nch = (qt + 1) * 2;

    pv_fill(sm, sb, 0, pg, sinv, b, 0, tid);
    CP_COMMIT;

    for (int c = 0; c < nch; c++) {
        if (c + 1 < nch) {
            __syncthreads();
            pv_fill(sm, sb, (c + 1) & 1, pg, sinv, b, (c + 1) * 64, tid);
            CP_COMMIT;
            CP_WAIT(1);
        } else {
            CP_WAIT(0);
        }
        __syncthreads();

        const uint32_t cb = sb + (c & 1) * PV_BUF;
#pragma unroll
        for (int kc = 0; kc < 4; kc++) {
            const int k0 = kc * 16;
            uint32_t bhi[8], blo[8];
#pragma unroll
            for (int jp = 0; jp < 2; jp++) {
                load_b_pair<PV_STRIDE>(cb + 2 * PV_TILE, nbase + jp * 16, k0, lane, &bhi[jp * 4]);
                load_b_pair<PV_STRIDE>(cb + 3 * PV_TILE, nbase + jp * 16, k0, lane, &blo[jp * 4]);
            }
#pragma unroll
            for (int mt = 0; mt < 2; mt++) {
                uint32_t ahi[4], alo[4];
                load_a_frag<PV_STRIDE>(cb, mbase + mt * 16, k0, lane, ahi);
                load_a_frag<PV_STRIDE>(cb + PV_TILE, mbase + mt * 16, k0, lane, alo);
#pragma unroll
                for (int nt = 0; nt < 4; nt++) {
                    MMA_BF16(acc[mt][nt], ahi[0], ahi[1], ahi[2], ahi[3], bhi[nt * 2], bhi[nt * 2 + 1]);
                    MMA_BF16(acc[mt][nt], ahi[0], ahi[1], ahi[2], ahi[3], blo[nt * 2], blo[nt * 2 + 1]);
                    MMA_BF16(acc[mt][nt], alo[0], alo[1], alo[2], alo[3], bhi[nt * 2], bhi[nt * 2 + 1]);
                }
            }
        }
    }

    float* og = ctx + ((size_t)b * SLEN + qt * 128) * BDIM;
#pragma unroll
    for (int mt = 0; mt < 2; mt++) {
        const int r0 = mbase + mt * 16 + (lane >> 2);
#pragma unroll
        for (int nt = 0; nt < 4; nt++) {
            const int col = nbase + nt * 8 + (lane & 3) * 2;
#pragma unroll
            for (int h = 0; h < 2; h++) {
                const int r = r0 + h * 8;
                *reinterpret_cast<float2*>(og + (size_t)r * BDIM + col) =
                    make_float2(acc[mt][nt][h * 2], acc[mt][nt][h * 2 + 1]);
            }
        }
    }
}

// ============================== launch ======================================
extern "C" void kernel_launch(void* const* d_in, const int* in_sizes, int n_in,
                              void* d_out, int out_size)
{
    const float* q = (const float*)d_in[0];
    const float* k = (const float*)d_in[1];
    const float* v = (const float*)d_in[2];

    float* ctx  = (float*)d_out;
    float* attn = ctx + (size_t)NBATCH * SLEN * BDIM;

    cudaFuncSetAttribute(vt_kernel,    cudaFuncAttributeMaxDynamicSharedMemorySize, VT_SMEM);
    cudaFuncSetAttribute(score_kernel, cudaFuncAttributeMaxDynamicSharedMemorySize, SC_SMEM);
    cudaFuncSetAttribute(pv_kernel,    cudaFuncAttributeMaxDynamicSharedMemorySize, PV_SMEM);

    zsum_kernel<<<(NBATCH * SLEN) / 1024, 256>>>();
    split_qk_kernel<<<(NBATCH * SLEN * BDIM) / (256 * 8), 256>>>(q, k);
    vt_kernel<<<dim3(SLEN / 128, NBATCH), 256, VT_SMEM>>>(v);
    score_kernel<<<dim3(SLEN / 128, SLEN / 128, NBATCH), 512, SC_SMEM>>>(attn);
    pv_kernel<<<dim3(SLEN / 128, NBATCH), 512, PV_SMEM>>>(attn, ctx);
}

// round 7
// speedup vs baseline: 2.9322x; 1.0914x over previous
#include <cuda_runtime.h>
#include <cuda_bf16.h>
#include <cstdint>
#include <cstddef>

#define SLEN 2048
#define BDIM 128
#define NBATCH 32
#define INV_TEMP 0.08838834764831845f   // 1/sqrt(128)

// ======================= device scratch (no cudaMalloc) ====================
__device__ __nv_bfloat16 g_q_hi[(size_t)NBATCH * SLEN * BDIM];
__device__ __nv_bfloat16 g_q_lo[(size_t)NBATCH * SLEN * BDIM];
__device__ __nv_bfloat16 g_k_hi[(size_t)NBATCH * SLEN * BDIM];
__device__ __nv_bfloat16 g_k_lo[(size_t)NBATCH * SLEN * BDIM];
__device__ __nv_bfloat16 g_vt_hi[(size_t)NBATCH * BDIM * SLEN];
__device__ __nv_bfloat16 g_vt_lo[(size_t)NBATCH * BDIM * SLEN];
__device__ float g_rowsum[(size_t)NBATCH * SLEN];

// =========================== helpers =======================================
__device__ __forceinline__ uint32_t smem_u32(const void* p) {
    uint32_t a;
    asm("{ .reg .u64 t; cvta.to.shared.u64 t, %1; cvt.u32.u64 %0, t; }"
        : "=r"(a) : "l"(p));
    return a;
}

#define LDSM_X4(r0, r1, r2, r3, addr) \
    asm volatile("ldmatrix.sync.aligned.m8n8.x4.shared.b16 {%0,%1,%2,%3}, [%4];" \
        : "=r"(r0), "=r"(r1), "=r"(r2), "=r"(r3) : "r"(addr))

#define MMA_BF16(c, a0, a1, a2, a3, b0, b1) \
    asm volatile("mma.sync.aligned.m16n8k16.row.col.f32.bf16.bf16.f32 " \
        "{%0,%1,%2,%3}, {%4,%5,%6,%7}, {%8,%9}, {%0,%1,%2,%3};" \
        : "+f"((c)[0]), "+f"((c)[1]), "+f"((c)[2]), "+f"((c)[3]) \
        : "r"(a0), "r"(a1), "r"(a2), "r"(a3), "r"(b0), "r"(b1))

#define CP_ASYNC16(dst, src) \
    asm volatile("cp.async.cg.shared.global [%0], [%1], 16;" \
        :: "r"(dst), "l"(src) : "memory")
#define CP_COMMIT  asm volatile("cp.async.commit_group;" ::: "memory")
#define CP_WAIT(n) asm volatile("cp.async.wait_group %0;" :: "n"(n) : "memory")

template <int STRIDE>
__device__ __forceinline__ void load_a_frag(uint32_t base, int mrow, int k0,
                                            int lane, uint32_t* a) {
    uint32_t off = (uint32_t)((mrow + (lane & 15)) * STRIDE + k0 + ((lane >> 4) << 3));
    LDSM_X4(a[0], a[1], a[2], a[3], base + (off << 1));
}

template <int STRIDE>
__device__ __forceinline__ void load_b_pair(uint32_t base, int nrow, int k0,
                                            int lane, uint32_t* b) {
    int g = lane >> 3;
    uint32_t off = (uint32_t)((nrow + ((g & 2) << 2) + (lane & 7)) * STRIDE
                              + k0 + ((g & 1) << 3));
    LDSM_X4(b[0], b[1], b[2], b[3], base + (off << 1));
}

// split 8 fp32 -> bf16 hi/lo packed uint4s
__device__ __forceinline__ void cvt8(const float4& x0, const float4& x1,
                                     uint4& hi, uint4& lo) {
    float v[8] = {x0.x, x0.y, x0.z, x0.w, x1.x, x1.y, x1.z, x1.w};
    uint32_t hb[8], lb[8];
#pragma unroll
    for (int j = 0; j < 8; j++) {
        __nv_bfloat16 h = __float2bfloat16(v[j]);
        float r = v[j] - __bfloat162float(h);
        __nv_bfloat16 l = __float2bfloat16(r);
        hb[j] = (uint32_t)__bfloat16_as_ushort(h);
        lb[j] = (uint32_t)__bfloat16_as_ushort(l);
    }
    hi = make_uint4(hb[0] | (hb[1] << 16), hb[2] | (hb[3] << 16),
                    hb[4] | (hb[5] << 16), hb[6] | (hb[7] << 16));
    lo = make_uint4(lb[0] | (lb[1] << 16), lb[2] | (lb[3] << 16),
                    lb[4] | (lb[5] << 16), lb[6] | (lb[7] << 16));
}

// fast exp on FMA/ALU pipes (no MUFU): 2^f poly deg-6, rel err ~1e-7
__device__ __forceinline__ float fast_exp(float x) {
    x = fmaxf(x, -87.0f);
    float y = x * 1.4426950408889634f;
    float t = y + 12582912.0f;
    int   ni = __float_as_int(t) - 0x4B400000;
    float nf = t - 12582912.0f;
    float f = y - nf;
    float p = 1.5403530e-4f;
    p = fmaf(p, f, 1.3333558e-3f);
    p = fmaf(p, f, 9.6181291e-3f);
    p = fmaf(p, f, 5.5504109e-2f);
    p = fmaf(p, f, 2.4022651e-1f);
    p = fmaf(p, f, 6.9314718e-1f);
    p = fmaf(p, f, 1.0f);
    return p * __int_as_float((ni + 127) << 23);
}

// shared tile geometry: K-chunks of 32, 4 slices per buffer, double buffered
#define TSTRIDE 40                          // bf16 elems per row (32 + 8 pad)
#define SLICE   (128 * TSTRIDE * 2)         // 10240 B
#define TBUF    (4 * SLICE)                 // 40960 B
#define TSMEM   (2 * TBUF)                  // 81920 B -> 2 CTAs/SM

// =============== prep 0: zero row sums ======================================
__global__ __launch_bounds__(256) void zsum_kernel() {
    const int idx = (blockIdx.x * 256 + threadIdx.x) * 4;
    *reinterpret_cast<float4*>(g_rowsum + idx) = make_float4(0.f, 0.f, 0.f, 0.f);
}

// =============== prep 1: split Q,K into bf16 hi/lo scratch ==================
__global__ __launch_bounds__(256) void split_qk_kernel(
    const float* __restrict__ Q, const float* __restrict__ K)
{
    const size_t base = ((size_t)blockIdx.x * 256 + threadIdx.x) * 8;
    uint4 hi, lo;
    float4 x0 = *reinterpret_cast<const float4*>(Q + base);
    float4 x1 = *reinterpret_cast<const float4*>(Q + base + 4);
    cvt8(x0, x1, hi, lo);
    *reinterpret_cast<uint4*>(g_q_hi + base) = hi;
    *reinterpret_cast<uint4*>(g_q_lo + base) = lo;
    x0 = *reinterpret_cast<const float4*>(K + base);
    x1 = *reinterpret_cast<const float4*>(K + base + 4);
    cvt8(x0, x1, hi, lo);
    *reinterpret_cast<uint4*>(g_k_hi + base) = hi;
    *reinterpret_cast<uint4*>(g_k_lo + base) = lo;
}

// =============== prep 2: V -> V^T bf16 hi/lo scratch ========================
#define VT_SMEM (128 * 132 * 4)
__global__ __launch_bounds__(256) void vt_kernel(const float* __restrict__ V) {
    extern __shared__ float ts[];   // [128][132]
    const int st = blockIdx.x, b = blockIdx.y, tid = threadIdx.x;
    const int s0 = st * 128;
    const float* vg = V + ((size_t)b * SLEN + s0) * BDIM;
#pragma unroll
    for (int i = 0; i < 16; i++) {
        int flat = tid + i * 256;
        int row = flat >> 5, c4 = flat & 31;
        float4 x = *reinterpret_cast<const float4*>(vg + (size_t)row * BDIM + c4 * 4);
        *reinterpret_cast<float4*>(ts + row * 132 + c4 * 4) = x;
    }
    __syncthreads();
#pragma unroll
    for (int i = 0; i < 8; i++) {
        int flat = tid + i * 256;
        int d = flat >> 4, sg = (flat & 15) * 8;
        uint32_t hb[8], lb[8];
#pragma unroll
        for (int j = 0; j < 8; j++) {
            float v = ts[(sg + j) * 132 + d];
            __nv_bfloat16 h = __float2bfloat16(v);
            float r = v - __bfloat162float(h);
            __nv_bfloat16 l = __float2bfloat16(r);
            hb[j] = (uint32_t)__bfloat16_as_ushort(h);
            lb[j] = (uint32_t)__bfloat16_as_ushort(l);
        }
        uint4 hi = make_uint4(hb[0] | (hb[1] << 16), hb[2] | (hb[3] << 16),
                              hb[4] | (hb[5] << 16), hb[6] | (hb[7] << 16));
        uint4 lo = make_uint4(lb[0] | (lb[1] << 16), lb[2] | (lb[3] << 16),
                              lb[4] | (lb[5] << 16), lb[6] | (lb[7] << 16));
        size_t idx = ((size_t)b * BDIM + d) * SLEN + s0 + sg;
        *reinterpret_cast<uint4*>(g_vt_hi + idx) = hi;
        *reinterpret_cast<uint4*>(g_vt_lo + idx) = lo;
    }
}

// ====== kernel 1: E = exp(causal(QK^T/sqrt(D))) + per-row sum atomics =======
// 512 threads, 2 CTAs/SM; double-buffered K-chunks of 32 via cp.async
__global__ __launch_bounds__(512, 2) void score_kernel(float* __restrict__ attn)
{
    extern __shared__ char sm[];
    const int kt = blockIdx.x, qt = blockIdx.y, b = blockIdx.z;
    const int tid = threadIdx.x, wid = tid >> 5, lane = tid & 31;

    float* out = attn + (size_t)b * SLEN * SLEN + (size_t)(qt * 128) * SLEN + kt * 128;

    if (kt > qt) {   // fully masked tile -> zeros
        const float4 z = make_float4(0.f, 0.f, 0.f, 0.f);
#pragma unroll
        for (int it = 0; it < 8; it++) {
            const int flat = tid + it * 512;
            const int r = flat >> 5, c4 = flat & 31;
            *reinterpret_cast<float4*>(out + (size_t)r * SLEN + c4 * 4) = z;
        }
        return;
    }

    const uint32_t sb = smem_u32(sm);
    const size_t qoff = ((size_t)b * SLEN + qt * 128) * BDIM;
    const size_t koff = ((size_t)b * SLEN + kt * 128) * BDIM;
    const __nv_bfloat16* srcs[4] = {g_q_hi + qoff, g_q_lo + qoff,
                                    g_k_hi + koff, g_k_lo + koff};

    // fill buffer `buf` with k-chunk c (cols [c*32, c*32+32))
    auto fill = [&](int buf, int c) {
#pragma unroll
        for (int i = 0; i < 4; i++) {
            const int flat = tid + i * 512;          // 0..2047
            const int tile = flat >> 9;              // 0..3
            const int idx  = flat & 511;
            const int row  = idx >> 2, u = idx & 3;  // 4 x 16B per row
            uint32_t dst = sb + buf * TBUF + tile * SLICE
                         + (uint32_t)(row * TSTRIDE + u * 8) * 2;
            CP_ASYNC16(dst, srcs[tile] + (size_t)row * BDIM + c * 32 + u * 8);
        }
    };

    const int wm = wid & 3;
    const int wn = wid >> 2;
    const int mbase = wm * 32;
    const int nbase = wn * 32;

    float acc[2][4][4] = {};

    fill(0, 0);
    CP_COMMIT;
    for (int c = 0; c < 4; c++) {
        if (c + 1 < 4) {
            __syncthreads();                 // prev compute on target buf done
            fill((c + 1) & 1, c + 1);
            CP_COMMIT;
            CP_WAIT(1);
        } else {
            CP_WAIT(0);
        }
        __syncthreads();

        const uint32_t cb = sb + (c & 1) * TBUF;
#pragma unroll
        for (int kc = 0; kc < 2; kc++) {
            const int k0 = kc * 16;
            uint32_t bhi[8], blo[8];
#pragma unroll
            for (int jp = 0; jp < 2; jp++) {
                load_b_pair<TSTRIDE>(cb + 2 * SLICE, nbase + jp * 16, k0, lane, &bhi[jp * 4]);
                load_b_pair<TSTRIDE>(cb + 3 * SLICE, nbase + jp * 16, k0, lane, &blo[jp * 4]);
            }
#pragma unroll
            for (int mt = 0; mt < 2; mt++) {
                uint32_t ahi[4], alo[4];
                load_a_frag<TSTRIDE>(cb, mbase + mt * 16, k0, lane, ahi);
                load_a_frag<TSTRIDE>(cb + SLICE, mbase + mt * 16, k0, lane, alo);
#pragma unroll
                for (int nt = 0; nt < 4; nt++) {
                    MMA_BF16(acc[mt][nt], ahi[0], ahi[1], ahi[2], ahi[3], bhi[nt * 2], bhi[nt * 2 + 1]);
                    MMA_BF16(acc[mt][nt], ahi[0], ahi[1], ahi[2], ahi[3], blo[nt * 2], blo[nt * 2 + 1]);
                    MMA_BF16(acc[mt][nt], alo[0], alo[1], alo[2], alo[3], bhi[nt * 2], bhi[nt * 2 + 1]);
                }
            }
        }
    }

    // epilogue: exp(scale*acc) + causal mask + store + row-sum atomics
    const bool diag = (kt == qt);
    float rsum[2][2] = {};
#pragma unroll
    for (int mt = 0; mt < 2; mt++) {
        const int r0 = mbase + mt * 16 + (lane >> 2);
#pragma unroll
        for (int nt = 0; nt < 4; nt++) {
            const int col = nbase + nt * 8 + (lane & 3) * 2;
#pragma unroll
            for (int h = 0; h < 2; h++) {
                const int r = r0 + h * 8;
                float v0 = fast_exp(acc[mt][nt][h * 2 + 0] * INV_TEMP);
                float v1 = fast_exp(acc[mt][nt][h * 2 + 1] * INV_TEMP);
                if (diag) {
                    if (col + 0 > r) v0 = 0.f;
                    if (col + 1 > r) v1 = 0.f;
                }
                rsum[mt][h] += v0 + v1;
                *reinterpret_cast<float2*>(out + (size_t)r * SLEN + col) =
                    make_float2(v0, v1);
            }
        }
    }
#pragma unroll
    for (int mt = 0; mt < 2; mt++)
#pragma unroll
        for (int h = 0; h < 2; h++) {
            rsum[mt][h] += __shfl_xor_sync(0xffffffffu, rsum[mt][h], 1);
            rsum[mt][h] += __shfl_xor_sync(0xffffffffu, rsum[mt][h], 2);
        }
    if ((lane & 3) == 0) {
        float* rs = g_rowsum + (size_t)b * SLEN + qt * 128;
#pragma unroll
        for (int mt = 0; mt < 2; mt++)
#pragma unroll
            for (int h = 0; h < 2; h++)
                atomicAdd(rs + mbase + mt * 16 + (lane >> 2) + h * 8, rsum[mt][h]);
    }
}

// ====== kernel 2: ctx = (E/rowsum) @ V; also writes normalized attn ========
// 512 threads, 2 CTAs/SM; double-buffered 32-key chunks
__global__ __launch_bounds__(512, 2) void pv_kernel(
    float* __restrict__ attn,
    float* __restrict__ ctx)
{
    extern __shared__ char sm[];
    __shared__ float sinv[128];
    const int qt = (int)gridDim.x - 1 - blockIdx.x;
    const int b  = blockIdx.y;
    const int tid = threadIdx.x, wid = tid >> 5, lane = tid & 31;

    const uint32_t sb = smem_u32(sm);
    float* pg = attn + (size_t)b * SLEN * SLEN + (size_t)(qt * 128) * SLEN;

    if (tid < 128)
        sinv[tid] = 1.0f / g_rowsum[(size_t)b * SLEN + qt * 128 + tid];
    __syncthreads();

    // fill buffer `buf` with key-chunk c (keys [c*32, c*32+32))
    auto fill = [&](int buf, int c) {
        const int k0 = c * 32;
        char* base = sm + buf * TBUF;
        const uint32_t sbase = sb + buf * TBUF;
#pragma unroll
        for (int i = 0; i < 2; i++) {
            const int flat = tid + i * 512;          // 0..1023
            if (flat < 512) {
                // P: 128 rows x 4 groups of 8 floats
                const int row = flat >> 2, g8 = (flat & 3) * 8;
                float* prow = pg + (size_t)row * SLEN + k0 + g8;
                float4 x0 = *reinterpret_cast<const float4*>(prow);
                float4 x1 = *reinterpret_cast<const float4*>(prow + 4);
                const float inv = sinv[row];
                x0.x *= inv; x0.y *= inv; x0.z *= inv; x0.w *= inv;
                x1.x *= inv; x1.y *= inv; x1.z *= inv; x1.w *= inv;
                *reinterpret_cast<float4*>(prow)     = x0;
                *reinterpret_cast<float4*>(prow + 4) = x1;
                uint4 hi, lo;
                cvt8(x0, x1, hi, lo);
                uint32_t dst = (uint32_t)(row * TSTRIDE + g8) * 2;
                *reinterpret_cast<uint4*>(base + dst)         = hi;
                *reinterpret_cast<uint4*>(base + SLICE + dst) = lo;
            } else {
                // V^T hi/lo via cp.async: 128 d-rows x 4 x 16B
                const int f = flat - 512;
                const int row = f >> 2, u = (f & 3) * 8;
                size_t vidx = ((size_t)b * BDIM + row) * SLEN + k0 + u;
                uint32_t dst = (uint32_t)(row * TSTRIDE + u) * 2;
                CP_ASYNC16(sbase + 2 * SLICE + dst, (const char*)(g_vt_hi + vidx));
                CP_ASYNC16(sbase + 3 * SLICE + dst, (const char*)(g_vt_lo + vidx));
            }
        }
    };

    const int wm = wid & 3;
    const int wn = wid >> 2;
    const int mbase = wm * 32;
    const int nbase = wn * 32;

    float acc[2][4][4] = {};
    const int nch = (qt + 1) * 4;

    fill(0, 0);
    CP_COMMIT;

    for (int c = 0; c < nch; c++) {
        if (c + 1 < nch) {
            __syncthreads();
            fill((c + 1) & 1, c + 1);
            CP_COMMIT;
            CP_WAIT(1);
        } else {
            CP_WAIT(0);
        }
        __syncthreads();

        const uint32_t cb = sb + (c & 1) * TBUF;
#pragma unroll
        for (int kc = 0; kc < 2; kc++) {
            const int k0 = kc * 16;
            uint32_t bhi[8], blo[8];
#pragma unroll
            for (int jp = 0; jp < 2; jp++) {
                load_b_pair<TSTRIDE>(cb + 2 * SLICE, nbase + jp * 16, k0, lane, &bhi[jp * 4]);
                load_b_pair<TSTRIDE>(cb + 3 * SLICE, nbase + jp * 16, k0, lane, &blo[jp * 4]);
            }
#pragma unroll
            for (int mt = 0; mt < 2; mt++) {
                uint32_t ahi[4], alo[4];
                load_a_frag<TSTRIDE>(cb, mbase + mt * 16, k0, lane, ahi);
                load_a_frag<TSTRIDE>(cb + SLICE, mbase + mt * 16, k0, lane, alo);
#pragma unroll
                for (int nt = 0; nt < 4; nt++) {
                    MMA_BF16(acc[mt][nt], ahi[0], ahi[1], ahi[2], ahi[3], bhi[nt * 2], bhi[nt * 2 + 1]);
                    MMA_BF16(acc[mt][nt], ahi[0], ahi[1], ahi[2], ahi[3], blo[nt * 2], blo[nt * 2 + 1]);
                    MMA_BF16(acc[mt][nt], alo[0], alo[1], alo[2], alo[3], bhi[nt * 2], bhi[nt * 2 + 1]);
                }
            }
        }
    }

    float* og = ctx + ((size_t)b * SLEN + qt * 128) * BDIM;
#pragma unroll
    for (int mt = 0; mt < 2; mt++) {
        const int r0 = mbase + mt * 16 + (lane >> 2);
#pragma unroll
        for (int nt = 0; nt < 4; nt++) {
            const int col = nbase + nt * 8 + (lane & 3) * 2;
#pragma unroll
            for (int h = 0; h < 2; h++) {
                const int r = r0 + h * 8;
                *reinterpret_cast<float2*>(og + (size_t)r * BDIM + col) =
                    make_float2(acc[mt][nt][h * 2], acc[mt][nt][h * 2 + 1]);
            }
        }
    }
}

// ============================== launch ======================================
extern "C" void kernel_launch(void* const* d_in, const int* in_sizes, int n_in,
                              void* d_out, int out_size)
{
    const float* q = (const float*)d_in[0];
    const float* k = (const float*)d_in[1];
    const float* v = (const float*)d_in[2];

    float* ctx  = (float*)d_out;
    float* attn = ctx + (size_t)NBATCH * SLEN * BDIM;

    cudaFuncSetAttribute(vt_kernel,    cudaFuncAttributeMaxDynamicSharedMemorySize, VT_SMEM);
    cudaFuncSetAttribute(score_kernel, cudaFuncAttributeMaxDynamicSharedMemorySize, TSMEM);
    cudaFuncSetAttribute(pv_kernel,    cudaFuncAttributeMaxDynamicSharedMemorySize, TSMEM);

    zsum_kernel<<<(NBATCH * SLEN) / 1024, 256>>>();
    split_qk_kernel<<<(NBATCH * SLEN * BDIM) / (256 * 8), 256>>>(q, k);
    vt_kernel<<<dim3(SLEN / 128, NBATCH), 256, VT_SMEM>>>(v);
    score_kernel<<<dim3(SLEN / 128, SLEN / 128, NBATCH), 512, TSMEM>>>(attn);
    pv_kernel<<<dim3(SLEN / 128, NBATCH), 512, TSMEM>>>(attn, ctx);
}